// round 1
// baseline (speedup 1.0000x reference)
#include <cuda_runtime.h>
#include <cuda_bf16.h>
#include <math.h>

// ---------------------------------------------------------------------------
// Problem constants (static per the reference setup_inputs)
// ---------------------------------------------------------------------------
#define BATCH 8
#define CH    192
#define HH    128
#define WW    128
#define HW    (HH*WW)            // 16384
#define TOK   (BATCH*HW)         // 131072
#define NH    8
#define HD    24
#define WS    8
#define FFN   768
#define NWIN  (BATCH*16*16)      // 2048 windows

// ---------------------------------------------------------------------------
// Scratch (device globals; no runtime allocation allowed)
// ---------------------------------------------------------------------------
__device__ float g_xn [TOK*CH];      // normalized activations
__device__ float g_qkv[TOK*3*CH];    // qkv
__device__ float g_att[TOK*CH];      // attention outputs (pre-proj)
__device__ float g_x1 [TOK*CH];      // residual stream (row-major [T,C])
__device__ float g_h1 [TOK*FFN];     // FFN hidden
__device__ float g_gram[NH*BATCH*HD*HD]; // 64 x 24 x 24
__device__ float g_A   [NH*BATCH*HD*HD];

// ---------------------------------------------------------------------------
// LayerNorm: from BCHW input -> row-major [T, C]
// one warp per token
// ---------------------------------------------------------------------------
__global__ void ln_bchw_kernel(const float* __restrict__ x,
                               const float* __restrict__ w,
                               const float* __restrict__ bb,
                               float* __restrict__ out) {
    int gwarp = (blockIdx.x * blockDim.x + threadIdx.x) >> 5;
    int lane  = threadIdx.x & 31;
    if (gwarp >= TOK) return;
    int b = gwarp >> 14;
    int l = gwarp & (HW - 1);
    const float* xp = x + ((size_t)b * CH << 14) + l;
    float v[6];
    float s = 0.f;
#pragma unroll
    for (int j = 0; j < 6; j++) {
        int c = lane + 32 * j;
        v[j] = xp[(size_t)c << 14];
        s += v[j];
    }
#pragma unroll
    for (int o = 16; o > 0; o >>= 1) s += __shfl_xor_sync(0xffffffffu, s, o);
    float mean = s * (1.f / CH);
    float s2 = 0.f;
#pragma unroll
    for (int j = 0; j < 6; j++) { float d = v[j] - mean; s2 += d * d; }
#pragma unroll
    for (int o = 16; o > 0; o >>= 1) s2 += __shfl_xor_sync(0xffffffffu, s2, o);
    float rstd = rsqrtf(s2 * (1.f / CH) + 1e-5f);
    float* op = out + (size_t)gwarp * CH;
#pragma unroll
    for (int j = 0; j < 6; j++) {
        int c = lane + 32 * j;
        op[c] = (v[j] - mean) * rstd * w[c] + bb[c];
    }
}

// LayerNorm from row-major [T,C] -> row-major [T,C]
__global__ void ln_row_kernel(const float* __restrict__ x,
                              const float* __restrict__ w,
                              const float* __restrict__ bb,
                              float* __restrict__ out) {
    int gwarp = (blockIdx.x * blockDim.x + threadIdx.x) >> 5;
    int lane  = threadIdx.x & 31;
    if (gwarp >= TOK) return;
    const float* xp = x + (size_t)gwarp * CH;
    float v[6];
    float s = 0.f;
#pragma unroll
    for (int j = 0; j < 6; j++) { v[j] = xp[lane + 32 * j]; s += v[j]; }
#pragma unroll
    for (int o = 16; o > 0; o >>= 1) s += __shfl_xor_sync(0xffffffffu, s, o);
    float mean = s * (1.f / CH);
    float s2 = 0.f;
#pragma unroll
    for (int j = 0; j < 6; j++) { float d = v[j] - mean; s2 += d * d; }
#pragma unroll
    for (int o = 16; o > 0; o >>= 1) s2 += __shfl_xor_sync(0xffffffffu, s2, o);
    float rstd = rsqrtf(s2 * (1.f / CH) + 1e-5f);
    float* op = out + (size_t)gwarp * CH;
#pragma unroll
    for (int j = 0; j < 6; j++) {
        int c = lane + 32 * j;
        op[c] = (v[j] - mean) * rstd * w[c] + bb[c];
    }
}

// ---------------------------------------------------------------------------
// Generic tiled SGEMM:  C[M,N] = A[M,K] @ W[N,K]^T  with fused epilogues
// MODE 0: C = acc
// MODE 1: C = gelu(acc + bias)                       (exact erf gelu)
// MODE 2: C = resid_bchw + gamma[n]*(acc + bias)     (stage-1 residual)
// MODE 3: C = resid_row  + gamma[n]*(acc + bias)     (stage-2, may be in-place)
// MODE 4: out_bchw = resid_row + gamma[n]*(acc+bias) (final write to d_out)
// ---------------------------------------------------------------------------
#define BM 128
#define BN 64
#define BK 16

template<int MODE>
__global__ __launch_bounds__(256)
void gemm_kernel(const float* __restrict__ A, const float* __restrict__ W,
                 float* __restrict__ Cout, int M, int N, int K,
                 const float* __restrict__ bias,
                 const float* __restrict__ gamma,
                 const float* __restrict__ resid) {
    __shared__ float As[BK][BM];
    __shared__ float Ws[BK][BN];

    int n0 = blockIdx.x * BN;
    int m0 = blockIdx.y * BM;
    int tid = threadIdx.x;
    int tx = tid & 15;   // n-dir, TN=4 -> 64
    int ty = tid >> 4;   // m-dir, TM=8 -> 128

    float acc[8][4];
#pragma unroll
    for (int i = 0; i < 8; i++)
#pragma unroll
        for (int j = 0; j < 4; j++) acc[i][j] = 0.f;

    int nK = K / BK;
    for (int kt = 0; kt < nK; kt++) {
        int k0 = kt * BK;
        // load A tile: 128 x 16 = 512 float4
#pragma unroll
        for (int r = 0; r < 2; r++) {
            int idx = tid + r * 256;
            int row = idx >> 2;
            int c4  = idx & 3;
            float4 v = *(const float4*)(A + (size_t)(m0 + row) * K + k0 + c4 * 4);
            As[c4 * 4 + 0][row] = v.x;
            As[c4 * 4 + 1][row] = v.y;
            As[c4 * 4 + 2][row] = v.z;
            As[c4 * 4 + 3][row] = v.w;
        }
        // load W tile: 64 x 16 = 256 float4
        {
            int row = tid >> 2;
            int c4  = tid & 3;
            float4 v = *(const float4*)(W + (size_t)(n0 + row) * K + k0 + c4 * 4);
            Ws[c4 * 4 + 0][row] = v.x;
            Ws[c4 * 4 + 1][row] = v.y;
            Ws[c4 * 4 + 2][row] = v.z;
            Ws[c4 * 4 + 3][row] = v.w;
        }
        __syncthreads();
#pragma unroll
        for (int k = 0; k < BK; k++) {
            float4 a0 = *(const float4*)&As[k][ty * 8];
            float4 a1 = *(const float4*)&As[k][ty * 8 + 4];
            float4 b0 = *(const float4*)&Ws[k][tx * 4];
            float a[8] = {a0.x, a0.y, a0.z, a0.w, a1.x, a1.y, a1.z, a1.w};
            float bv[4] = {b0.x, b0.y, b0.z, b0.w};
#pragma unroll
            for (int i = 0; i < 8; i++)
#pragma unroll
                for (int j = 0; j < 4; j++) acc[i][j] += a[i] * bv[j];
        }
        __syncthreads();
    }

#pragma unroll
    for (int i = 0; i < 8; i++) {
        int m = m0 + ty * 8 + i;
#pragma unroll
        for (int j = 0; j < 4; j++) {
            int n = n0 + tx * 4 + j;
            float v = acc[i][j];
            if (MODE == 0) {
                Cout[(size_t)m * N + n] = v;
            } else if (MODE == 1) {
                v += bias[n];
                v = 0.5f * v * (1.0f + erff(v * 0.70710678118654752f));
                Cout[(size_t)m * N + n] = v;
            } else if (MODE == 2) {
                int b = m >> 14, l = m & (HW - 1);
                float r = resid[((size_t)(b * CH + n) << 14) + l];
                Cout[(size_t)m * N + n] = r + gamma[n] * (v + bias[n]);
            } else if (MODE == 3) {
                float r = resid[(size_t)m * N + n];
                Cout[(size_t)m * N + n] = r + gamma[n] * (v + bias[n]);
            } else { // MODE 4
                int b = m >> 14, l = m & (HW - 1);
                float r = resid[(size_t)m * N + n];
                Cout[((size_t)(b * CH + n) << 14) + l] = r + gamma[n] * (v + bias[n]);
            }
        }
    }
}

// ---------------------------------------------------------------------------
// Window attention: one block = (window, head); 64 threads = 64 query tokens
// ---------------------------------------------------------------------------
__global__ __launch_bounds__(64)
void win_attn_kernel(const float* __restrict__ qkv,
                     const float* __restrict__ table,
                     float* __restrict__ out) {
    int h   = blockIdx.x & 7;
    int wid = blockIdx.x >> 3;
    int b   = wid >> 8;
    int rem = wid & 255;
    int wy  = rem >> 4, wx = rem & 15;

    int i  = threadIdx.x;          // 0..63 query index within window
    int iy = i >> 3, ix = i & 7;
    int t  = (b << 14) + ((wy * 8 + iy) << 7) + wx * 8 + ix;

    __shared__ float ks[64][24];
    __shared__ float vs[64][24];
    __shared__ float bt[225];
    for (int p = i; p < 225; p += 64) bt[p] = table[p * NH + h];

    const float* row = qkv + (size_t)t * (3 * CH) + h * HD;
    float q[24];
#pragma unroll
    for (int d = 0; d < HD; d++) {
        q[d]     = row[d];
        ks[i][d] = row[CH + d];
        vs[i][d] = row[2 * CH + d];
    }
    __syncthreads();

    const float scale = 0.20412414523193154f; // 1/sqrt(24)
    float sc[64];
    float mx = -1e30f;
#pragma unroll 4
    for (int j = 0; j < 64; j++) {
        int jy = j >> 3, jx = j & 7;
        float dot = 0.f;
#pragma unroll
        for (int d = 0; d < HD; d++) dot += q[d] * ks[j][d];
        dot = dot * scale + bt[(iy - jy + 7) * 15 + (ix - jx + 7)];
        sc[j] = dot;
        mx = fmaxf(mx, dot);
    }
    float sum = 0.f;
#pragma unroll 4
    for (int j = 0; j < 64; j++) { sc[j] = __expf(sc[j] - mx); sum += sc[j]; }
    float inv = 1.f / sum;

    float accum[24];
#pragma unroll
    for (int d = 0; d < HD; d++) accum[d] = 0.f;
#pragma unroll 2
    for (int j = 0; j < 64; j++) {
        float p = sc[j];
#pragma unroll
        for (int d = 0; d < HD; d++) accum[d] += p * vs[j][d];
    }
    float* op = out + (size_t)t * CH + h * HD;
#pragma unroll
    for (int d = 0; d < HD; d++) op[d] = accum[d] * inv;
}

// ---------------------------------------------------------------------------
// Channel attention: gram matrix G[bh][d][e] = sum_l q[l,d] k[l,e]
// grid (64, 16) blocks of 576 threads; each thread owns one (d,e) pair
// ---------------------------------------------------------------------------
__global__ __launch_bounds__(576)
void ca_gram_kernel(const float* __restrict__ qkv, float* __restrict__ gram) {
    int bh = blockIdx.x;
    int b = bh >> 3, h = bh & 7;
    int tid = threadIdx.x;        // 0..575
    int d = tid / 24, e = tid - d * 24;

    __shared__ float qs[64][24];
    __shared__ float ks[64][24];

    const int chunk = HW / 16;    // 1024 tokens per block
    int l0 = blockIdx.y * chunk;
    float accum = 0.f;
    for (int tile = 0; tile < chunk; tile += 64) {
        for (int p = tid; p < 64 * 24; p += 576) {
            int tok = p / 24, dd = p - tok * 24;
            size_t base = (size_t)((b << 14) + l0 + tile + tok) * (3 * CH) + h * HD + dd;
            qs[tok][dd] = qkv[base];
            ks[tok][dd] = qkv[base + CH];
        }
        __syncthreads();
#pragma unroll 8
        for (int tok = 0; tok < 64; tok++) accum += qs[tok][d] * ks[tok][e];
        __syncthreads();
    }
    atomicAdd(&gram[bh * (HD * HD) + tid], accum);
}

__global__ void zero_gram_kernel(float* __restrict__ gram) {
    int i = blockIdx.x * blockDim.x + threadIdx.x;
    if (i < NH * BATCH * HD * HD) gram[i] = 0.f;
}

// softmax over last dim of 24x24 gram, with scale
__global__ void ca_softmax_kernel(const float* __restrict__ gram, float* __restrict__ A) {
    int bh = blockIdx.x;
    int d = threadIdx.x;
    if (d >= HD) return;
    const float scale = 0.20412414523193154f;
    float r[24];
    float mx = -1e30f;
#pragma unroll
    for (int e = 0; e < HD; e++) {
        r[e] = gram[bh * (HD * HD) + d * HD + e] * scale;
        mx = fmaxf(mx, r[e]);
    }
    float sum = 0.f;
#pragma unroll
    for (int e = 0; e < HD; e++) { r[e] = __expf(r[e] - mx); sum += r[e]; }
    float inv = 1.f / sum;
#pragma unroll
    for (int e = 0; e < HD; e++) A[bh * (HD * HD) + d * HD + e] = r[e] * inv;
}

// apply: out[t][h*24+d] = sum_e A[bh][d][e] * v[t][h*24+e]
// grid (B, 512): block covers 32 tokens; 256 threads -> 8 threads/token (one head each)
__global__ __launch_bounds__(256)
void ca_out_kernel(const float* __restrict__ qkv, const float* __restrict__ A,
                   float* __restrict__ out) {
    int b  = blockIdx.x;
    int l0 = blockIdx.y * 32;
    int tid = threadIdx.x;
    __shared__ float vs[32][192];
    for (int p = tid; p < 32 * 192; p += 256) {
        int tok = p / 192, c = p - tok * 192;
        vs[tok][c] = qkv[(size_t)((b << 14) + l0 + tok) * (3 * CH) + 2 * CH + c];
    }
    __syncthreads();
    int tok = tid >> 3;
    int h   = tid & 7;
    int t   = (b << 14) + l0 + tok;
    const float* Ah = A + (b * 8 + h) * (HD * HD);
    float* op = out + (size_t)t * CH + h * HD;
#pragma unroll
    for (int d = 0; d < HD; d++) {
        float s = 0.f;
#pragma unroll
        for (int e = 0; e < HD; e++) s += Ah[d * HD + e] * vs[tok][h * HD + e];
        op[d] = s;
    }
}

// ---------------------------------------------------------------------------
// Launch
// ---------------------------------------------------------------------------
extern "C" void kernel_launch(void* const* d_in, const int* in_sizes, int n_in,
                              void* d_out, int out_size) {
    const float* x          = (const float*)d_in[0];
    const float* sa_norm_w  = (const float*)d_in[1];
    const float* sa_norm_b  = (const float*)d_in[2];
    const float* sa_qkv_w   = (const float*)d_in[3];
    const float* sa_proj_w  = (const float*)d_in[4];
    const float* sa_proj_b  = (const float*)d_in[5];
    const float* sa_bias_t  = (const float*)d_in[6];
    const float* ca_norm_w  = (const float*)d_in[7];
    const float* ca_norm_b  = (const float*)d_in[8];
    const float* ca_qkv_w   = (const float*)d_in[9];
    const float* ca_proj_w  = (const float*)d_in[10];
    const float* ca_proj_b  = (const float*)d_in[11];
    const float* ffn_norm_w = (const float*)d_in[12];
    const float* ffn_norm_b = (const float*)d_in[13];
    const float* ffn_w1     = (const float*)d_in[14];
    const float* ffn_b1     = (const float*)d_in[15];
    const float* ffn_w2     = (const float*)d_in[16];
    const float* ffn_w2b    = (const float*)d_in[17];
    const float* gamma1     = (const float*)d_in[18];
    const float* gamma2     = (const float*)d_in[19];
    const float* gamma3     = (const float*)d_in[20];
    float* out = (float*)d_out;

    float *xn, *qkv, *att, *x1, *h1, *gram, *Amat;
    cudaGetSymbolAddress((void**)&xn,   g_xn);
    cudaGetSymbolAddress((void**)&qkv,  g_qkv);
    cudaGetSymbolAddress((void**)&att,  g_att);
    cudaGetSymbolAddress((void**)&x1,   g_x1);
    cudaGetSymbolAddress((void**)&h1,   g_h1);
    cudaGetSymbolAddress((void**)&gram, g_gram);
    cudaGetSymbolAddress((void**)&Amat, g_A);

    const int lnBlocks = TOK / 8; // 8 warps (tokens) per 256-thread block

    // ---- stage 1: window attention ----
    ln_bchw_kernel<<<lnBlocks, 256>>>(x, sa_norm_w, sa_norm_b, xn);
    gemm_kernel<0><<<dim3(3 * CH / BN, TOK / BM), 256>>>(
        xn, sa_qkv_w, qkv, TOK, 3 * CH, CH, nullptr, nullptr, nullptr);
    win_attn_kernel<<<NWIN * NH, 64>>>(qkv, sa_bias_t, att);
    gemm_kernel<2><<<dim3(CH / BN, TOK / BM), 256>>>(
        att, sa_proj_w, x1, TOK, CH, CH, sa_proj_b, gamma1, x);

    // ---- stage 2: channel attention ----
    ln_row_kernel<<<lnBlocks, 256>>>(x1, ca_norm_w, ca_norm_b, xn);
    gemm_kernel<0><<<dim3(3 * CH / BN, TOK / BM), 256>>>(
        xn, ca_qkv_w, qkv, TOK, 3 * CH, CH, nullptr, nullptr, nullptr);
    zero_gram_kernel<<<(NH * BATCH * HD * HD + 255) / 256, 256>>>(gram);
    ca_gram_kernel<<<dim3(NH * BATCH, 16), 576>>>(qkv, gram);
    ca_softmax_kernel<<<NH * BATCH, 32>>>(gram, Amat);
    ca_out_kernel<<<dim3(BATCH, HW / 32), 256>>>(qkv, Amat, att);
    gemm_kernel<3><<<dim3(CH / BN, TOK / BM), 256>>>(
        att, ca_proj_w, x1, TOK, CH, CH, ca_proj_b, gamma2, x1); // in-place residual

    // ---- stage 3: gated FFN ----
    ln_row_kernel<<<lnBlocks, 256>>>(x1, ffn_norm_w, ffn_norm_b, xn);
    gemm_kernel<1><<<dim3(FFN / BN, TOK / BM), 256>>>(
        xn, ffn_w1, h1, TOK, FFN, CH, ffn_b1, nullptr, nullptr);
    gemm_kernel<4><<<dim3(CH / BN, TOK / BM), 256>>>(
        h1, ffn_w2, out, TOK, CH, FFN, ffn_w2b, gamma3, x1);
}

// round 2
// speedup vs baseline: 1.4726x; 1.4726x over previous
#include <cuda_runtime.h>
#include <cuda_bf16.h>
#include <math.h>
#include <stdint.h>

// ---------------------------------------------------------------------------
// Problem constants (static per the reference setup_inputs)
// ---------------------------------------------------------------------------
#define BATCH 8
#define CH    192
#define HH    128
#define WW    128
#define HW    (HH*WW)            // 16384
#define TOK   (BATCH*HW)         // 131072
#define NH    8
#define HD    24
#define WS    8
#define FFN   768
#define NWIN  (BATCH*16*16)      // 2048 windows

// ---------------------------------------------------------------------------
// Scratch (device globals; no runtime allocation allowed)
// ---------------------------------------------------------------------------
__device__ float g_xn [TOK*CH];      // normalized activations
__device__ float g_qkv[TOK*3*CH];    // qkv
__device__ float g_att[TOK*CH];      // attention outputs (pre-proj)
__device__ float g_x1 [TOK*CH];      // residual stream (row-major [T,C])
__device__ float g_h1 [TOK*FFN];     // FFN hidden
__device__ float g_gram[NH*BATCH*HD*HD]; // 64 x 24 x 24
__device__ float g_A   [NH*BATCH*HD*HD];

// ---------------------------------------------------------------------------
// LayerNorm: from BCHW input -> row-major [T, C]   (one warp per token)
// ---------------------------------------------------------------------------
__global__ void ln_bchw_kernel(const float* __restrict__ x,
                               const float* __restrict__ w,
                               const float* __restrict__ bb,
                               float* __restrict__ out) {
    int gwarp = (blockIdx.x * blockDim.x + threadIdx.x) >> 5;
    int lane  = threadIdx.x & 31;
    if (gwarp >= TOK) return;
    int b = gwarp >> 14;
    int l = gwarp & (HW - 1);
    const float* xp = x + ((size_t)b * CH << 14) + l;
    float v[6];
    float s = 0.f;
#pragma unroll
    for (int j = 0; j < 6; j++) {
        int c = lane + 32 * j;
        v[j] = xp[(size_t)c << 14];
        s += v[j];
    }
#pragma unroll
    for (int o = 16; o > 0; o >>= 1) s += __shfl_xor_sync(0xffffffffu, s, o);
    float mean = s * (1.f / CH);
    float s2 = 0.f;
#pragma unroll
    for (int j = 0; j < 6; j++) { float d = v[j] - mean; s2 += d * d; }
#pragma unroll
    for (int o = 16; o > 0; o >>= 1) s2 += __shfl_xor_sync(0xffffffffu, s2, o);
    float rstd = rsqrtf(s2 * (1.f / CH) + 1e-5f);
    float* op = out + (size_t)gwarp * CH;
#pragma unroll
    for (int j = 0; j < 6; j++) {
        int c = lane + 32 * j;
        op[c] = (v[j] - mean) * rstd * w[c] + bb[c];
    }
}

// LayerNorm from row-major [T,C] -> row-major [T,C]
__global__ void ln_row_kernel(const float* __restrict__ x,
                              const float* __restrict__ w,
                              const float* __restrict__ bb,
                              float* __restrict__ out) {
    int gwarp = (blockIdx.x * blockDim.x + threadIdx.x) >> 5;
    int lane  = threadIdx.x & 31;
    if (gwarp >= TOK) return;
    const float* xp = x + (size_t)gwarp * CH;
    float v[6];
    float s = 0.f;
#pragma unroll
    for (int j = 0; j < 6; j++) { v[j] = xp[lane + 32 * j]; s += v[j]; }
#pragma unroll
    for (int o = 16; o > 0; o >>= 1) s += __shfl_xor_sync(0xffffffffu, s, o);
    float mean = s * (1.f / CH);
    float s2 = 0.f;
#pragma unroll
    for (int j = 0; j < 6; j++) { float d = v[j] - mean; s2 += d * d; }
#pragma unroll
    for (int o = 16; o > 0; o >>= 1) s2 += __shfl_xor_sync(0xffffffffu, s2, o);
    float rstd = rsqrtf(s2 * (1.f / CH) + 1e-5f);
    float* op = out + (size_t)gwarp * CH;
#pragma unroll
    for (int j = 0; j < 6; j++) {
        int c = lane + 32 * j;
        op[c] = (v[j] - mean) * rstd * w[c] + bb[c];
    }
}

// ---------------------------------------------------------------------------
// TF32 tensor-core GEMM:  C[M,N] = A[M,K] @ W[N,K]^T  with fused epilogues
// MODE 0: C = acc
// MODE 1: C = gelu(acc + bias)                       (exact erf gelu)
// MODE 2: C = resid_bchw + gamma[n]*(acc + bias)     (stage-1 residual)
// MODE 3: C = resid_row  + gamma[n]*(acc + bias)     (stage-2, may be in-place)
// MODE 4: out_bchw = resid_row + gamma[n]*(acc+bias) (final write to d_out)
//
// Block tile 128x64x16, 256 threads = 8 warps in 4(m) x 2(n); warp tile 32x32
// = 2 x 4 mma.m16n8k8 tiles. Double-buffered smem, pad-8 strides for
// conflict-free fragment loads (addr % 32 = 8k+n, all distinct per warp).
// ---------------------------------------------------------------------------
#define BM 128
#define BN 64
#define BK 16
#define ASTRIDE (BM + 8)   // 136
#define WSTRIDE (BN + 8)   // 72

__device__ __forceinline__ uint32_t f2tf32(float x) {
    uint32_t r;
    asm("cvt.rna.tf32.f32 %0, %1;" : "=r"(r) : "f"(x));
    return r;
}

template<int MODE>
__global__ __launch_bounds__(256)
void gemm_tf32_kernel(const float* __restrict__ A, const float* __restrict__ W,
                      float* __restrict__ Cout, int M, int N, int K,
                      const float* __restrict__ bias,
                      const float* __restrict__ gamma,
                      const float* __restrict__ resid) {
    __shared__ float As[2][BK][ASTRIDE];
    __shared__ float Ws[2][BK][WSTRIDE];

    const int n0 = blockIdx.x * BN;
    const int m0 = blockIdx.y * BM;
    const int tid  = threadIdx.x;
    const int lane = tid & 31;
    const int wid  = tid >> 5;
    const int warpM = wid & 3;      // 0..3 -> m offset *32
    const int warpN = wid >> 2;     // 0..1 -> n offset *32

    // global->reg staging indices
    const int aRow = tid >> 2;          // 0..63 (two rows: +0, +64)
    const int aC4  = tid & 3;           // k-quad
    const int wRow = tid >> 2;          // 0..63
    const int wC4  = tid & 3;

    float4 aReg[2], wReg;

    float acc[2][4][4];
#pragma unroll
    for (int i = 0; i < 2; i++)
#pragma unroll
        for (int j = 0; j < 4; j++)
#pragma unroll
            for (int q = 0; q < 4; q++) acc[i][j][q] = 0.f;

    const int nK = K / BK;

    // prefetch tile 0
    {
        const float* Ap = A + (size_t)(m0 + aRow) * K + aC4 * 4;
        aReg[0] = *(const float4*)(Ap);
        aReg[1] = *(const float4*)(Ap + (size_t)64 * K);
        wReg    = *(const float4*)(W + (size_t)(n0 + wRow) * K + wC4 * 4);
    }

    int buf = 0;
    for (int kt = 0; kt < nK; kt++) {
        // store staged tile (with tf32 rounding)
        {
            float av0[4] = {aReg[0].x, aReg[0].y, aReg[0].z, aReg[0].w};
            float av1[4] = {aReg[1].x, aReg[1].y, aReg[1].z, aReg[1].w};
            float wv [4] = {wReg.x, wReg.y, wReg.z, wReg.w};
#pragma unroll
            for (int q = 0; q < 4; q++) {
                As[buf][aC4 * 4 + q][aRow]      = __uint_as_float(f2tf32(av0[q]));
                As[buf][aC4 * 4 + q][aRow + 64] = __uint_as_float(f2tf32(av1[q]));
                Ws[buf][wC4 * 4 + q][wRow]      = __uint_as_float(f2tf32(wv[q]));
            }
        }
        __syncthreads();

        // prefetch next tile
        if (kt + 1 < nK) {
            int k0 = (kt + 1) * BK;
            const float* Ap = A + (size_t)(m0 + aRow) * K + k0 + aC4 * 4;
            aReg[0] = *(const float4*)(Ap);
            aReg[1] = *(const float4*)(Ap + (size_t)64 * K);
            wReg    = *(const float4*)(W + (size_t)(n0 + wRow) * K + k0 + wC4 * 4);
        }

        // compute on current buffer
#pragma unroll
        for (int ks = 0; ks < BK; ks += 8) {
            uint32_t a[2][4], b[4][2];
            const int kr = ks + (lane & 3);
            const int rb = warpM * 32 + (lane >> 2);
#pragma unroll
            for (int i = 0; i < 2; i++) {
                int r = rb + i * 16;
                a[i][0] = __float_as_uint(As[buf][kr    ][r    ]);
                a[i][1] = __float_as_uint(As[buf][kr    ][r + 8]);
                a[i][2] = __float_as_uint(As[buf][kr + 4][r    ]);
                a[i][3] = __float_as_uint(As[buf][kr + 4][r + 8]);
            }
#pragma unroll
            for (int j = 0; j < 4; j++) {
                int n = warpN * 32 + j * 8 + (lane >> 2);
                b[j][0] = __float_as_uint(Ws[buf][kr    ][n]);
                b[j][1] = __float_as_uint(Ws[buf][kr + 4][n]);
            }
#pragma unroll
            for (int i = 0; i < 2; i++)
#pragma unroll
                for (int j = 0; j < 4; j++) {
                    asm volatile(
                        "mma.sync.aligned.m16n8k8.row.col.f32.tf32.tf32.f32 "
                        "{%0,%1,%2,%3},{%4,%5,%6,%7},{%8,%9},{%0,%1,%2,%3};"
                        : "+f"(acc[i][j][0]), "+f"(acc[i][j][1]),
                          "+f"(acc[i][j][2]), "+f"(acc[i][j][3])
                        : "r"(a[i][0]), "r"(a[i][1]), "r"(a[i][2]), "r"(a[i][3]),
                          "r"(b[j][0]), "r"(b[j][1]));
                }
        }
        buf ^= 1;
    }

    // ---- epilogue ----
    const int rq = lane >> 2;          // 0..7
    const int cq = (lane & 3) * 2;     // 0,2,4,6
#pragma unroll
    for (int i = 0; i < 2; i++) {
#pragma unroll
        for (int j = 0; j < 4; j++) {
#pragma unroll
            for (int half = 0; half < 2; half++) {      // row, row+8
#pragma unroll
                for (int cc = 0; cc < 2; cc++) {        // col, col+1
                    int m = m0 + warpM * 32 + i * 16 + rq + half * 8;
                    int n = n0 + warpN * 32 + j * 8 + cq + cc;
                    float v = acc[i][j][half * 2 + cc];
                    if (MODE == 0) {
                        Cout[(size_t)m * N + n] = v;
                    } else if (MODE == 1) {
                        v += bias[n];
                        v = 0.5f * v * (1.0f + erff(v * 0.70710678118654752f));
                        Cout[(size_t)m * N + n] = v;
                    } else if (MODE == 2) {
                        int bb_ = m >> 14, l = m & (HW - 1);
                        float r = resid[((size_t)(bb_ * CH + n) << 14) + l];
                        Cout[(size_t)m * N + n] = r + gamma[n] * (v + bias[n]);
                    } else if (MODE == 3) {
                        float r = resid[(size_t)m * N + n];
                        Cout[(size_t)m * N + n] = r + gamma[n] * (v + bias[n]);
                    } else { // MODE 4
                        int bb_ = m >> 14, l = m & (HW - 1);
                        float r = resid[(size_t)m * N + n];
                        Cout[((size_t)(bb_ * CH + n) << 14) + l] = r + gamma[n] * (v + bias[n]);
                    }
                }
            }
        }
    }
}

// ---------------------------------------------------------------------------
// Window attention: one block = (window, head); 64 threads = 64 query tokens
// ---------------------------------------------------------------------------
__global__ __launch_bounds__(64)
void win_attn_kernel(const float* __restrict__ qkv,
                     const float* __restrict__ table,
                     float* __restrict__ out) {
    int h   = blockIdx.x & 7;
    int wid = blockIdx.x >> 3;
    int b   = wid >> 8;
    int rem = wid & 255;
    int wy  = rem >> 4, wx = rem & 15;

    int i  = threadIdx.x;          // 0..63 query index within window
    int iy = i >> 3, ix = i & 7;
    int t  = (b << 14) + ((wy * 8 + iy) << 7) + wx * 8 + ix;

    __shared__ float ks[64][24];
    __shared__ float vs[64][24];
    __shared__ float bt[225];
    for (int p = i; p < 225; p += 64) bt[p] = table[p * NH + h];

    const float* row = qkv + (size_t)t * (3 * CH) + h * HD;
    float q[24];
#pragma unroll
    for (int d = 0; d < HD; d++) {
        q[d]     = row[d];
        ks[i][d] = row[CH + d];
        vs[i][d] = row[2 * CH + d];
    }
    __syncthreads();

    const float scale = 0.20412414523193154f; // 1/sqrt(24)
    float sc[64];
    float mx = -1e30f;
#pragma unroll 4
    for (int j = 0; j < 64; j++) {
        int jy = j >> 3, jx = j & 7;
        float dot = 0.f;
#pragma unroll
        for (int d = 0; d < HD; d++) dot += q[d] * ks[j][d];
        dot = dot * scale + bt[(iy - jy + 7) * 15 + (ix - jx + 7)];
        sc[j] = dot;
        mx = fmaxf(mx, dot);
    }
    float sum = 0.f;
#pragma unroll 4
    for (int j = 0; j < 64; j++) { sc[j] = __expf(sc[j] - mx); sum += sc[j]; }
    float inv = 1.f / sum;

    float accum[24];
#pragma unroll
    for (int d = 0; d < HD; d++) accum[d] = 0.f;
#pragma unroll 2
    for (int j = 0; j < 64; j++) {
        float p = sc[j];
#pragma unroll
        for (int d = 0; d < HD; d++) accum[d] += p * vs[j][d];
    }
    float* op = out + (size_t)t * CH + h * HD;
#pragma unroll
    for (int d = 0; d < HD; d++) op[d] = accum[d] * inv;
}

// ---------------------------------------------------------------------------
// Channel attention: gram matrix G[bh][d][e] = sum_l q[l,d] k[l,e]
// ---------------------------------------------------------------------------
__global__ __launch_bounds__(576)
void ca_gram_kernel(const float* __restrict__ qkv, float* __restrict__ gram) {
    int bh = blockIdx.x;
    int b = bh >> 3, h = bh & 7;
    int tid = threadIdx.x;        // 0..575
    int d = tid / 24, e = tid - d * 24;

    __shared__ float qs[64][24];
    __shared__ float ks[64][24];

    const int chunk = HW / 16;    // 1024 tokens per block
    int l0 = blockIdx.y * chunk;
    float accum = 0.f;
    for (int tile = 0; tile < chunk; tile += 64) {
        for (int p = tid; p < 64 * 24; p += 576) {
            int tok = p / 24, dd = p - tok * 24;
            size_t base = (size_t)((b << 14) + l0 + tile + tok) * (3 * CH) + h * HD + dd;
            qs[tok][dd] = qkv[base];
            ks[tok][dd] = qkv[base + CH];
        }
        __syncthreads();
#pragma unroll 8
        for (int tok = 0; tok < 64; tok++) accum += qs[tok][d] * ks[tok][e];
        __syncthreads();
    }
    atomicAdd(&gram[bh * (HD * HD) + tid], accum);
}

__global__ void zero_gram_kernel(float* __restrict__ gram) {
    int i = blockIdx.x * blockDim.x + threadIdx.x;
    if (i < NH * BATCH * HD * HD) gram[i] = 0.f;
}

// softmax over last dim of 24x24 gram, with scale
__global__ void ca_softmax_kernel(const float* __restrict__ gram, float* __restrict__ A) {
    int bh = blockIdx.x;
    int d = threadIdx.x;
    if (d >= HD) return;
    const float scale = 0.20412414523193154f;
    float r[24];
    float mx = -1e30f;
#pragma unroll
    for (int e = 0; e < HD; e++) {
        r[e] = gram[bh * (HD * HD) + d * HD + e] * scale;
        mx = fmaxf(mx, r[e]);
    }
    float sum = 0.f;
#pragma unroll
    for (int e = 0; e < HD; e++) { r[e] = __expf(r[e] - mx); sum += r[e]; }
    float inv = 1.f / sum;
#pragma unroll
    for (int e = 0; e < HD; e++) A[bh * (HD * HD) + d * HD + e] = r[e] * inv;
}

// apply: out[t][h*24+d] = sum_e A[bh][d][e] * v[t][h*24+e]
__global__ __launch_bounds__(256)
void ca_out_kernel(const float* __restrict__ qkv, const float* __restrict__ A,
                   float* __restrict__ out) {
    int b  = blockIdx.x;
    int l0 = blockIdx.y * 32;
    int tid = threadIdx.x;
    __shared__ float vs[32][192];
    for (int p = tid; p < 32 * 192; p += 256) {
        int tok = p / 192, c = p - tok * 192;
        vs[tok][c] = qkv[(size_t)((b << 14) + l0 + tok) * (3 * CH) + 2 * CH + c];
    }
    __syncthreads();
    int tok = tid >> 3;
    int h   = tid & 7;
    int t   = (b << 14) + l0 + tok;
    const float* Ah = A + (b * 8 + h) * (HD * HD);
    float* op = out + (size_t)t * CH + h * HD;
#pragma unroll
    for (int d = 0; d < HD; d++) {
        float s = 0.f;
#pragma unroll
        for (int e = 0; e < HD; e++) s += Ah[d * HD + e] * vs[tok][h * HD + e];
        op[d] = s;
    }
}

// ---------------------------------------------------------------------------
// Launch
// ---------------------------------------------------------------------------
extern "C" void kernel_launch(void* const* d_in, const int* in_sizes, int n_in,
                              void* d_out, int out_size) {
    const float* x          = (const float*)d_in[0];
    const float* sa_norm_w  = (const float*)d_in[1];
    const float* sa_norm_b  = (const float*)d_in[2];
    const float* sa_qkv_w   = (const float*)d_in[3];
    const float* sa_proj_w  = (const float*)d_in[4];
    const float* sa_proj_b  = (const float*)d_in[5];
    const float* sa_bias_t  = (const float*)d_in[6];
    const float* ca_norm_w  = (const float*)d_in[7];
    const float* ca_norm_b  = (const float*)d_in[8];
    const float* ca_qkv_w   = (const float*)d_in[9];
    const float* ca_proj_w  = (const float*)d_in[10];
    const float* ca_proj_b  = (const float*)d_in[11];
    const float* ffn_norm_w = (const float*)d_in[12];
    const float* ffn_norm_b = (const float*)d_in[13];
    const float* ffn_w1     = (const float*)d_in[14];
    const float* ffn_b1     = (const float*)d_in[15];
    const float* ffn_w2     = (const float*)d_in[16];
    const float* ffn_w2b    = (const float*)d_in[17];
    const float* gamma1     = (const float*)d_in[18];
    const float* gamma2     = (const float*)d_in[19];
    const float* gamma3     = (const float*)d_in[20];
    float* out = (float*)d_out;

    float *xn, *qkv, *att, *x1, *h1, *gram, *Amat;
    cudaGetSymbolAddress((void**)&xn,   g_xn);
    cudaGetSymbolAddress((void**)&qkv,  g_qkv);
    cudaGetSymbolAddress((void**)&att,  g_att);
    cudaGetSymbolAddress((void**)&x1,   g_x1);
    cudaGetSymbolAddress((void**)&h1,   g_h1);
    cudaGetSymbolAddress((void**)&gram, g_gram);
    cudaGetSymbolAddress((void**)&Amat, g_A);

    const int lnBlocks = TOK / 8; // 8 warps (tokens) per 256-thread block

    // ---- stage 1: window attention ----
    ln_bchw_kernel<<<lnBlocks, 256>>>(x, sa_norm_w, sa_norm_b, xn);
    gemm_tf32_kernel<0><<<dim3(3 * CH / BN, TOK / BM), 256>>>(
        xn, sa_qkv_w, qkv, TOK, 3 * CH, CH, nullptr, nullptr, nullptr);
    win_attn_kernel<<<NWIN * NH, 64>>>(qkv, sa_bias_t, att);
    gemm_tf32_kernel<2><<<dim3(CH / BN, TOK / BM), 256>>>(
        att, sa_proj_w, x1, TOK, CH, CH, sa_proj_b, gamma1, x);

    // ---- stage 2: channel attention ----
    ln_row_kernel<<<lnBlocks, 256>>>(x1, ca_norm_w, ca_norm_b, xn);
    gemm_tf32_kernel<0><<<dim3(3 * CH / BN, TOK / BM), 256>>>(
        xn, ca_qkv_w, qkv, TOK, 3 * CH, CH, nullptr, nullptr, nullptr);
    zero_gram_kernel<<<(NH * BATCH * HD * HD + 255) / 256, 256>>>(gram);
    ca_gram_kernel<<<dim3(NH * BATCH, 16), 576>>>(qkv, gram);
    ca_softmax_kernel<<<NH * BATCH, 32>>>(gram, Amat);
    ca_out_kernel<<<dim3(BATCH, HW / 32), 256>>>(qkv, Amat, att);
    gemm_tf32_kernel<3><<<dim3(CH / BN, TOK / BM), 256>>>(
        att, ca_proj_w, x1, TOK, CH, CH, ca_proj_b, gamma2, x1); // in-place residual

    // ---- stage 3: gated FFN ----
    ln_row_kernel<<<lnBlocks, 256>>>(x1, ffn_norm_w, ffn_norm_b, xn);
    gemm_tf32_kernel<1><<<dim3(FFN / BN, TOK / BM), 256>>>(
        xn, ffn_w1, h1, TOK, FFN, CH, ffn_b1, nullptr, nullptr);
    gemm_tf32_kernel<4><<<dim3(CH / BN, TOK / BM), 256>>>(
        h1, ffn_w2, out, TOK, CH, FFN, ffn_w2b, gamma3, x1);
}

// round 4
// speedup vs baseline: 1.6015x; 1.0875x over previous
#include <cuda_runtime.h>
#include <cuda_bf16.h>
#include <math.h>
#include <stdint.h>

// ---------------------------------------------------------------------------
// Problem constants
// ---------------------------------------------------------------------------
#define BATCH 8
#define CH    192
#define HH    128
#define WW    128
#define HW    (HH*WW)            // 16384
#define TOK   (BATCH*HW)         // 131072
#define NH    8
#define HD    24
#define WS    8
#define FFN   768
#define NWIN  (BATCH*16*16)      // 2048 windows

// ---------------------------------------------------------------------------
// Scratch (device globals; no runtime allocation allowed)
// ---------------------------------------------------------------------------
__device__ float g_xn [TOK*CH];
__device__ float g_qkv[TOK*3*CH];
__device__ float g_att[TOK*CH];
__device__ float g_x1 [TOK*CH];
__device__ float g_h1 [TOK*FFN];
__device__ float g_gram[NH*BATCH*HD*HD];
__device__ float g_A   [NH*BATCH*HD*HD];

// ---------------------------------------------------------------------------
// LayerNorms
// ---------------------------------------------------------------------------
__global__ void ln_bchw_kernel(const float* __restrict__ x,
                               const float* __restrict__ w,
                               const float* __restrict__ bb,
                               float* __restrict__ out) {
    int gwarp = (blockIdx.x * blockDim.x + threadIdx.x) >> 5;
    int lane  = threadIdx.x & 31;
    if (gwarp >= TOK) return;
    int b = gwarp >> 14;
    int l = gwarp & (HW - 1);
    const float* xp = x + ((size_t)b * CH << 14) + l;
    float v[6];
    float s = 0.f;
#pragma unroll
    for (int j = 0; j < 6; j++) {
        int c = lane + 32 * j;
        v[j] = xp[(size_t)c << 14];
        s += v[j];
    }
#pragma unroll
    for (int o = 16; o > 0; o >>= 1) s += __shfl_xor_sync(0xffffffffu, s, o);
    float mean = s * (1.f / CH);
    float s2 = 0.f;
#pragma unroll
    for (int j = 0; j < 6; j++) { float d = v[j] - mean; s2 += d * d; }
#pragma unroll
    for (int o = 16; o > 0; o >>= 1) s2 += __shfl_xor_sync(0xffffffffu, s2, o);
    float rstd = rsqrtf(s2 * (1.f / CH) + 1e-5f);
    float* op = out + (size_t)gwarp * CH;
#pragma unroll
    for (int j = 0; j < 6; j++) {
        int c = lane + 32 * j;
        op[c] = (v[j] - mean) * rstd * w[c] + bb[c];
    }
}

__global__ void ln_row_kernel(const float* __restrict__ x,
                              const float* __restrict__ w,
                              const float* __restrict__ bb,
                              float* __restrict__ out) {
    int gwarp = (blockIdx.x * blockDim.x + threadIdx.x) >> 5;
    int lane  = threadIdx.x & 31;
    if (gwarp >= TOK) return;
    const float* xp = x + (size_t)gwarp * CH;
    float v[6];
    float s = 0.f;
#pragma unroll
    for (int j = 0; j < 6; j++) { v[j] = xp[lane + 32 * j]; s += v[j]; }
#pragma unroll
    for (int o = 16; o > 0; o >>= 1) s += __shfl_xor_sync(0xffffffffu, s, o);
    float mean = s * (1.f / CH);
    float s2 = 0.f;
#pragma unroll
    for (int j = 0; j < 6; j++) { float d = v[j] - mean; s2 += d * d; }
#pragma unroll
    for (int o = 16; o > 0; o >>= 1) s2 += __shfl_xor_sync(0xffffffffu, s2, o);
    float rstd = rsqrtf(s2 * (1.f / CH) + 1e-5f);
    float* op = out + (size_t)gwarp * CH;
#pragma unroll
    for (int j = 0; j < 6; j++) {
        int c = lane + 32 * j;
        op[c] = (v[j] - mean) * rstd * w[c] + bb[c];
    }
}

// ---------------------------------------------------------------------------
// TF32 tensor-core GEMM:  C[M,N] = A[M,K] @ W[N,K]^T, fused epilogues.
// CTA tile 128x192x16; 6 warps (2m x 3n), warp tile 64x64 (4x8 m16n8k8).
// k-pair-permuted smem layout so each fragment pair (k, k+4) is one LDS.64.
//   kp(k) = (k>>3)*8 + (k&3)*2 + ((k>>2)&1)
// Row stride 24 words -> conflict-free fragment loads per half-warp phase.
// MODE 0: C = acc
// MODE 1: C = gelu(acc + bias)
// MODE 2: C = resid_bchw + gamma[n]*(acc + bias)
// MODE 3: C = resid_row  + gamma[n]*(acc + bias)   (in-place safe)
// MODE 4: out_bchw = resid_row + gamma[n]*(acc + bias)
// ---------------------------------------------------------------------------
#define BM 128
#define BN 192
#define BK 16
#define SSTR 24                      // word stride per row
#define A_WORDS (BM * SSTR)          // 3072 per buffer
#define B_WORDS (BN * SSTR)          // 4608 per buffer
#define SMEM_WORDS (2 * A_WORDS + 2 * B_WORDS)   // 15360 words = 61440 B

__device__ __forceinline__ uint32_t f2tf32(float x) {
    uint32_t r;
    asm("cvt.rna.tf32.f32 %0, %1;" : "=r"(r) : "f"(x));
    return r;
}

__device__ __forceinline__ int kperm(int k) {
    return ((k >> 3) << 3) + ((k & 3) << 1) + ((k >> 2) & 1);
}

template<int MODE>
__global__ __launch_bounds__(192, 1)
void gemm_tf32_kernel(const float* __restrict__ A, const float* __restrict__ W,
                      float* __restrict__ Cout, int M, int N, int K,
                      const float* __restrict__ bias,
                      const float* __restrict__ gamma,
                      const float* __restrict__ resid) {
    extern __shared__ float sm[];
    float* Asm = sm;                       // [2][BM][SSTR]
    float* Bsm = sm + 2 * A_WORDS;         // [2][BN][SSTR]

    const int n0 = blockIdx.x * BN;
    const int m0 = blockIdx.y * BM;
    const int tid  = threadIdx.x;
    const int lane = tid & 31;
    const int wid  = tid >> 5;       // 0..5
    const int wm   = wid & 1;        // m-warp: 0..1  (64 rows each)
    const int wn   = wid >> 1;       // n-warp: 0..2  (64 cols each)

    // staging indices
    const int sRow = tid >> 2;       // 0..47 step base
    const int sC4  = tid & 3;        // k quad
    const int kpBase[4] = { kperm(sC4*4+0), kperm(sC4*4+1), kperm(sC4*4+2), kperm(sC4*4+3) };

    float4 aR[3], bR[4];

    float acc[4][8][4];
#pragma unroll
    for (int i = 0; i < 4; i++)
#pragma unroll
        for (int j = 0; j < 8; j++)
#pragma unroll
            for (int q = 0; q < 4; q++) acc[i][j][q] = 0.f;

    const int nK = K / BK;

    // ---- prefetch chunk 0 ----
    {
#pragma unroll
        for (int it = 0; it < 3; it++) {
            int row = sRow + it * 48;
            if (it < 2 || row < BM)
                aR[it] = *(const float4*)(A + (size_t)(m0 + row) * K + sC4 * 4);
        }
#pragma unroll
        for (int it = 0; it < 4; it++) {
            int row = sRow + it * 48;
            bR[it] = *(const float4*)(W + (size_t)(n0 + row) * K + sC4 * 4);
        }
    }

    int buf = 0;
    // ---- store chunk 0 ----
    {
#pragma unroll
        for (int it = 0; it < 3; it++) {
            int row = sRow + it * 48;
            if (it == 2 && row >= BM) continue;
            float vv[4] = {aR[it].x, aR[it].y, aR[it].z, aR[it].w};
            float* dst = Asm + row * SSTR;
#pragma unroll
            for (int q = 0; q < 4; q++) dst[kpBase[q]] = __uint_as_float(f2tf32(vv[q]));
        }
#pragma unroll
        for (int it = 0; it < 4; it++) {
            int row = sRow + it * 48;
            float vv[4] = {bR[it].x, bR[it].y, bR[it].z, bR[it].w};
            float* dst = Bsm + row * SSTR;
#pragma unroll
            for (int q = 0; q < 4; q++) dst[kpBase[q]] = __uint_as_float(f2tf32(vv[q]));
        }
    }
    __syncthreads();

    const int fr = lane >> 2;          // 0..7
    const int fc = (lane & 3) << 1;    // 0,2,4,6

    for (int kt = 0; kt < nK; kt++) {
        // prefetch next chunk
        if (kt + 1 < nK) {
            int k0 = (kt + 1) * BK;
#pragma unroll
            for (int it = 0; it < 3; it++) {
                int row = sRow + it * 48;
                if (it < 2 || row < BM)
                    aR[it] = *(const float4*)(A + (size_t)(m0 + row) * K + k0 + sC4 * 4);
            }
#pragma unroll
            for (int it = 0; it < 4; it++) {
                int row = sRow + it * 48;
                bR[it] = *(const float4*)(W + (size_t)(n0 + row) * K + k0 + sC4 * 4);
            }
        }

        const float* Ab = Asm + buf * A_WORDS;
        const float* Bb = Bsm + buf * B_WORDS;

#pragma unroll
        for (int g = 0; g < 2; g++) {
            float2 aF[4][2];
#pragma unroll
            for (int i = 0; i < 4; i++) {
                int r = wm * 64 + i * 16 + fr;
                aF[i][0] = *(const float2*)(Ab + r * SSTR + g * 8 + fc);
                aF[i][1] = *(const float2*)(Ab + (r + 8) * SSTR + g * 8 + fc);
            }
            float2 bF[8];
#pragma unroll
            for (int j = 0; j < 8; j++) {
                int c = wn * 64 + j * 8 + fr;
                bF[j] = *(const float2*)(Bb + c * SSTR + g * 8 + fc);
            }
#pragma unroll
            for (int i = 0; i < 4; i++)
#pragma unroll
                for (int j = 0; j < 8; j++) {
                    asm volatile(
                        "mma.sync.aligned.m16n8k8.row.col.f32.tf32.tf32.f32 "
                        "{%0,%1,%2,%3},{%4,%5,%6,%7},{%8,%9},{%0,%1,%2,%3};"
                        : "+f"(acc[i][j][0]), "+f"(acc[i][j][1]),
                          "+f"(acc[i][j][2]), "+f"(acc[i][j][3])
                        : "r"(__float_as_uint(aF[i][0].x)), "r"(__float_as_uint(aF[i][1].x)),
                          "r"(__float_as_uint(aF[i][0].y)), "r"(__float_as_uint(aF[i][1].y)),
                          "r"(__float_as_uint(bF[j].x)),    "r"(__float_as_uint(bF[j].y)));
                }
        }

        // store next chunk into other buffer
        if (kt + 1 < nK) {
            float* Ad = Asm + (buf ^ 1) * A_WORDS;
            float* Bd = Bsm + (buf ^ 1) * B_WORDS;
#pragma unroll
            for (int it = 0; it < 3; it++) {
                int row = sRow + it * 48;
                if (it == 2 && row >= BM) continue;
                float vv[4] = {aR[it].x, aR[it].y, aR[it].z, aR[it].w};
                float* dst = Ad + row * SSTR;
#pragma unroll
                for (int q = 0; q < 4; q++) dst[kpBase[q]] = __uint_as_float(f2tf32(vv[q]));
            }
#pragma unroll
            for (int it = 0; it < 4; it++) {
                int row = sRow + it * 48;
                float vv[4] = {bR[it].x, bR[it].y, bR[it].z, bR[it].w};
                float* dst = Bd + row * SSTR;
#pragma unroll
                for (int q = 0; q < 4; q++) dst[kpBase[q]] = __uint_as_float(f2tf32(vv[q]));
            }
            __syncthreads();
            buf ^= 1;
        }
    }

    // ---- epilogue ----
    const int rq = lane >> 2;
    const int cq = (lane & 3) * 2;
#pragma unroll
    for (int i = 0; i < 4; i++) {
#pragma unroll
        for (int j = 0; j < 8; j++) {
#pragma unroll
            for (int half = 0; half < 2; half++) {
#pragma unroll
                for (int cc = 0; cc < 2; cc++) {
                    int m = m0 + wm * 64 + i * 16 + rq + half * 8;
                    int n = n0 + wn * 64 + j * 8 + cq + cc;
                    float v = acc[i][j][half * 2 + cc];
                    if (MODE == 0) {
                        Cout[(size_t)m * N + n] = v;
                    } else if (MODE == 1) {
                        v += bias[n];
                        v = 0.5f * v * (1.0f + erff(v * 0.70710678118654752f));
                        Cout[(size_t)m * N + n] = v;
                    } else if (MODE == 2) {
                        int bb_ = m >> 14, l = m & (HW - 1);
                        float r = resid[((size_t)(bb_ * CH + n) << 14) + l];
                        Cout[(size_t)m * N + n] = r + gamma[n] * (v + bias[n]);
                    } else if (MODE == 3) {
                        float r = resid[(size_t)m * N + n];
                        Cout[(size_t)m * N + n] = r + gamma[n] * (v + bias[n]);
                    } else { // MODE 4
                        int bb_ = m >> 14, l = m & (HW - 1);
                        float r = resid[(size_t)m * N + n];
                        Cout[((size_t)(bb_ * CH + n) << 14) + l] = r + gamma[n] * (v + bias[n]);
                    }
                }
            }
        }
    }
}

// ---------------------------------------------------------------------------
// Window attention
// ---------------------------------------------------------------------------
__global__ __launch_bounds__(64)
void win_attn_kernel(const float* __restrict__ qkv,
                     const float* __restrict__ table,
                     float* __restrict__ out) {
    int h   = blockIdx.x & 7;
    int wid = blockIdx.x >> 3;
    int b   = wid >> 8;
    int rem = wid & 255;
    int wy  = rem >> 4, wx = rem & 15;

    int i  = threadIdx.x;
    int iy = i >> 3, ix = i & 7;
    int t  = (b << 14) + ((wy * 8 + iy) << 7) + wx * 8 + ix;

    __shared__ float ks[64][24];
    __shared__ float vs[64][24];
    __shared__ float bt[225];
    for (int p = i; p < 225; p += 64) bt[p] = table[p * NH + h];

    const float* row = qkv + (size_t)t * (3 * CH) + h * HD;
    float q[24];
#pragma unroll
    for (int d = 0; d < HD; d++) {
        q[d]     = row[d];
        ks[i][d] = row[CH + d];
        vs[i][d] = row[2 * CH + d];
    }
    __syncthreads();

    const float scale = 0.20412414523193154f;
    float sc[64];
    float mx = -1e30f;
#pragma unroll 4
    for (int j = 0; j < 64; j++) {
        int jy = j >> 3, jx = j & 7;
        float dot = 0.f;
#pragma unroll
        for (int d = 0; d < HD; d++) dot += q[d] * ks[j][d];
        dot = dot * scale + bt[(iy - jy + 7) * 15 + (ix - jx + 7)];
        sc[j] = dot;
        mx = fmaxf(mx, dot);
    }
    float sum = 0.f;
#pragma unroll 4
    for (int j = 0; j < 64; j++) { sc[j] = __expf(sc[j] - mx); sum += sc[j]; }
    float inv = 1.f / sum;

    float accum[24];
#pragma unroll
    for (int d = 0; d < HD; d++) accum[d] = 0.f;
#pragma unroll 2
    for (int j = 0; j < 64; j++) {
        float p = sc[j];
#pragma unroll
        for (int d = 0; d < HD; d++) accum[d] += p * vs[j][d];
    }
    float* op = out + (size_t)t * CH + h * HD;
#pragma unroll
    for (int d = 0; d < HD; d++) op[d] = accum[d] * inv;
}

// ---------------------------------------------------------------------------
// Channel attention
// ---------------------------------------------------------------------------
__global__ __launch_bounds__(576)
void ca_gram_kernel(const float* __restrict__ qkv, float* __restrict__ gram) {
    int bh = blockIdx.x;
    int b = bh >> 3, h = bh & 7;
    int tid = threadIdx.x;
    int d = tid / 24, e = tid - d * 24;

    __shared__ float qs[64][24];
    __shared__ float ks[64][24];

    const int chunk = HW / 16;
    int l0 = blockIdx.y * chunk;
    float accum = 0.f;
    for (int tile = 0; tile < chunk; tile += 64) {
        for (int p = tid; p < 64 * 24; p += 576) {
            int tok = p / 24, dd = p - tok * 24;
            size_t base = (size_t)((b << 14) + l0 + tile + tok) * (3 * CH) + h * HD + dd;
            qs[tok][dd] = qkv[base];
            ks[tok][dd] = qkv[base + CH];
        }
        __syncthreads();
#pragma unroll 8
        for (int tok = 0; tok < 64; tok++) accum += qs[tok][d] * ks[tok][e];
        __syncthreads();
    }
    atomicAdd(&gram[bh * (HD * HD) + tid], accum);
}

__global__ void zero_gram_kernel(float* __restrict__ gram) {
    int i = blockIdx.x * blockDim.x + threadIdx.x;
    if (i < NH * BATCH * HD * HD) gram[i] = 0.f;
}

__global__ void ca_softmax_kernel(const float* __restrict__ gram, float* __restrict__ A) {
    int bh = blockIdx.x;
    int d = threadIdx.x;
    if (d >= HD) return;
    const float scale = 0.20412414523193154f;
    float r[24];
    float mx = -1e30f;
#pragma unroll
    for (int e = 0; e < HD; e++) {
        r[e] = gram[bh * (HD * HD) + d * HD + e] * scale;
        mx = fmaxf(mx, r[e]);
    }
    float sum = 0.f;
#pragma unroll
    for (int e = 0; e < HD; e++) { r[e] = __expf(r[e] - mx); sum += r[e]; }
    float inv = 1.f / sum;
#pragma unroll
    for (int e = 0; e < HD; e++) A[bh * (HD * HD) + d * HD + e] = r[e] * inv;
}

__global__ __launch_bounds__(256)
void ca_out_kernel(const float* __restrict__ qkv, const float* __restrict__ A,
                   float* __restrict__ out) {
    int b  = blockIdx.x;
    int l0 = blockIdx.y * 32;
    int tid = threadIdx.x;
    __shared__ float vs[32][192];
    for (int p = tid; p < 32 * 192; p += 256) {
        int tok = p / 192, c = p - tok * 192;
        vs[tok][c] = qkv[(size_t)((b << 14) + l0 + tok) * (3 * CH) + 2 * CH + c];
    }
    __syncthreads();
    int tok = tid >> 3;
    int h   = tid & 7;
    int t   = (b << 14) + l0 + tok;
    const float* Ah = A + (b * 8 + h) * (HD * HD);
    float* op = out + (size_t)t * CH + h * HD;
#pragma unroll
    for (int d = 0; d < HD; d++) {
        float s = 0.f;
#pragma unroll
        for (int e = 0; e < HD; e++) s += Ah[d * HD + e] * vs[tok][h * HD + e];
        op[d] = s;
    }
}

// ---------------------------------------------------------------------------
// Launch
// ---------------------------------------------------------------------------
extern "C" void kernel_launch(void* const* d_in, const int* in_sizes, int n_in,
                              void* d_out, int out_size) {
    const float* x          = (const float*)d_in[0];
    const float* sa_norm_w  = (const float*)d_in[1];
    const float* sa_norm_b  = (const float*)d_in[2];
    const float* sa_qkv_w   = (const float*)d_in[3];
    const float* sa_proj_w  = (const float*)d_in[4];
    const float* sa_proj_b  = (const float*)d_in[5];
    const float* sa_bias_t  = (const float*)d_in[6];
    const float* ca_norm_w  = (const float*)d_in[7];
    const float* ca_norm_b  = (const float*)d_in[8];
    const float* ca_qkv_w   = (const float*)d_in[9];
    const float* ca_proj_w  = (const float*)d_in[10];
    const float* ca_proj_b  = (const float*)d_in[11];
    const float* ffn_norm_w = (const float*)d_in[12];
    const float* ffn_norm_b = (const float*)d_in[13];
    const float* ffn_w1     = (const float*)d_in[14];
    const float* ffn_b1     = (const float*)d_in[15];
    const float* ffn_w2     = (const float*)d_in[16];
    const float* ffn_w2b    = (const float*)d_in[17];
    const float* gamma1     = (const float*)d_in[18];
    const float* gamma2     = (const float*)d_in[19];
    const float* gamma3     = (const float*)d_in[20];
    float* out = (float*)d_out;

    float *xn, *qkv, *att, *x1, *h1, *gram, *Amat;
    cudaGetSymbolAddress((void**)&xn,   g_xn);
    cudaGetSymbolAddress((void**)&qkv,  g_qkv);
    cudaGetSymbolAddress((void**)&att,  g_att);
    cudaGetSymbolAddress((void**)&x1,   g_x1);
    cudaGetSymbolAddress((void**)&h1,   g_h1);
    cudaGetSymbolAddress((void**)&gram, g_gram);
    cudaGetSymbolAddress((void**)&Amat, g_A);

    // Opt-in to 60KB dynamic smem (idempotent, no static guards per harness rules)
    const int smemB = SMEM_WORDS * 4;  // 61440
    cudaFuncSetAttribute(gemm_tf32_kernel<0>, cudaFuncAttributeMaxDynamicSharedMemorySize, smemB);
    cudaFuncSetAttribute(gemm_tf32_kernel<1>, cudaFuncAttributeMaxDynamicSharedMemorySize, smemB);
    cudaFuncSetAttribute(gemm_tf32_kernel<2>, cudaFuncAttributeMaxDynamicSharedMemorySize, smemB);
    cudaFuncSetAttribute(gemm_tf32_kernel<3>, cudaFuncAttributeMaxDynamicSharedMemorySize, smemB);
    cudaFuncSetAttribute(gemm_tf32_kernel<4>, cudaFuncAttributeMaxDynamicSharedMemorySize, smemB);

    const int lnBlocks = TOK / 8;

    // ---- stage 1: window attention ----
    ln_bchw_kernel<<<lnBlocks, 256>>>(x, sa_norm_w, sa_norm_b, xn);
    gemm_tf32_kernel<0><<<dim3(3 * CH / BN, TOK / BM), 192, smemB>>>(
        xn, sa_qkv_w, qkv, TOK, 3 * CH, CH, nullptr, nullptr, nullptr);
    win_attn_kernel<<<NWIN * NH, 64>>>(qkv, sa_bias_t, att);
    gemm_tf32_kernel<2><<<dim3(CH / BN, TOK / BM), 192, smemB>>>(
        att, sa_proj_w, x1, TOK, CH, CH, sa_proj_b, gamma1, x);

    // ---- stage 2: channel attention ----
    ln_row_kernel<<<lnBlocks, 256>>>(x1, ca_norm_w, ca_norm_b, xn);
    gemm_tf32_kernel<0><<<dim3(3 * CH / BN, TOK / BM), 192, smemB>>>(
        xn, ca_qkv_w, qkv, TOK, 3 * CH, CH, nullptr, nullptr, nullptr);
    zero_gram_kernel<<<(NH * BATCH * HD * HD + 255) / 256, 256>>>(gram);
    ca_gram_kernel<<<dim3(NH * BATCH, 16), 576>>>(qkv, gram);
    ca_softmax_kernel<<<NH * BATCH, 32>>>(gram, Amat);
    ca_out_kernel<<<dim3(BATCH, HW / 32), 256>>>(qkv, Amat, att);
    gemm_tf32_kernel<3><<<dim3(CH / BN, TOK / BM), 192, smemB>>>(
        att, ca_proj_w, x1, TOK, CH, CH, ca_proj_b, gamma2, x1);

    // ---- stage 3: gated FFN ----
    ln_row_kernel<<<lnBlocks, 256>>>(x1, ffn_norm_w, ffn_norm_b, xn);
    gemm_tf32_kernel<1><<<dim3(FFN / BN, TOK / BM), 192, smemB>>>(
        xn, ffn_w1, h1, TOK, FFN, CH, ffn_b1, nullptr, nullptr);
    gemm_tf32_kernel<4><<<dim3(CH / BN, TOK / BM), 192, smemB>>>(
        h1, ffn_w2, out, TOK, CH, FFN, ffn_w2b, gamma3, x1);
}

// round 5
// speedup vs baseline: 1.6233x; 1.0136x over previous
#include <cuda_runtime.h>
#include <cuda_bf16.h>
#include <math.h>
#include <stdint.h>

// ---------------------------------------------------------------------------
// Problem constants
// ---------------------------------------------------------------------------
#define BATCH 8
#define CH    192
#define HH    128
#define WW    128
#define HW    (HH*WW)            // 16384
#define TOK   (BATCH*HW)         // 131072
#define NH    8
#define HD    24
#define WS    8
#define FFN   768
#define NWIN  (BATCH*16*16)      // 2048 windows

// ---------------------------------------------------------------------------
// Scratch (device globals; no runtime allocation allowed)
// ---------------------------------------------------------------------------
__device__ float g_xn [TOK*CH];
__device__ float g_qkv[TOK*3*CH];
__device__ float g_att[TOK*CH];
__device__ float g_x1 [TOK*CH];
__device__ float g_h1 [TOK*FFN];
__device__ float g_gram[NH*BATCH*HD*HD];
__device__ float g_A   [NH*BATCH*HD*HD];

// ---------------------------------------------------------------------------
// LayerNorms
// ---------------------------------------------------------------------------
__global__ void ln_bchw_kernel(const float* __restrict__ x,
                               const float* __restrict__ w,
                               const float* __restrict__ bb,
                               float* __restrict__ out) {
    int gwarp = (blockIdx.x * blockDim.x + threadIdx.x) >> 5;
    int lane  = threadIdx.x & 31;
    if (gwarp >= TOK) return;
    int b = gwarp >> 14;
    int l = gwarp & (HW - 1);
    const float* xp = x + ((size_t)b * CH << 14) + l;
    float v[6];
    float s = 0.f;
#pragma unroll
    for (int j = 0; j < 6; j++) {
        int c = lane + 32 * j;
        v[j] = xp[(size_t)c << 14];
        s += v[j];
    }
#pragma unroll
    for (int o = 16; o > 0; o >>= 1) s += __shfl_xor_sync(0xffffffffu, s, o);
    float mean = s * (1.f / CH);
    float s2 = 0.f;
#pragma unroll
    for (int j = 0; j < 6; j++) { float d = v[j] - mean; s2 += d * d; }
#pragma unroll
    for (int o = 16; o > 0; o >>= 1) s2 += __shfl_xor_sync(0xffffffffu, s2, o);
    float rstd = rsqrtf(s2 * (1.f / CH) + 1e-5f);
    float* op = out + (size_t)gwarp * CH;
#pragma unroll
    for (int j = 0; j < 6; j++) {
        int c = lane + 32 * j;
        op[c] = (v[j] - mean) * rstd * w[c] + bb[c];
    }
}

__global__ void ln_row_kernel(const float* __restrict__ x,
                              const float* __restrict__ w,
                              const float* __restrict__ bb,
                              float* __restrict__ out) {
    int gwarp = (blockIdx.x * blockDim.x + threadIdx.x) >> 5;
    int lane  = threadIdx.x & 31;
    if (gwarp >= TOK) return;
    const float* xp = x + (size_t)gwarp * CH;
    float v[6];
    float s = 0.f;
#pragma unroll
    for (int j = 0; j < 6; j++) { v[j] = xp[lane + 32 * j]; s += v[j]; }
#pragma unroll
    for (int o = 16; o > 0; o >>= 1) s += __shfl_xor_sync(0xffffffffu, s, o);
    float mean = s * (1.f / CH);
    float s2 = 0.f;
#pragma unroll
    for (int j = 0; j < 6; j++) { float d = v[j] - mean; s2 += d * d; }
#pragma unroll
    for (int o = 16; o > 0; o >>= 1) s2 += __shfl_xor_sync(0xffffffffu, s2, o);
    float rstd = rsqrtf(s2 * (1.f / CH) + 1e-5f);
    float* op = out + (size_t)gwarp * CH;
#pragma unroll
    for (int j = 0; j < 6; j++) {
        int c = lane + 32 * j;
        op[c] = (v[j] - mean) * rstd * w[c] + bb[c];
    }
}

// ---------------------------------------------------------------------------
// TF32 tensor-core GEMM:  C[M,N] = A[M,K] @ W[N,K]^T, fused epilogues.
// CTA tile 128x192x16; 8 warps (2m x 4n), warp tile 64x48 (4x6 m16n8k8).
// 96 accumulator regs/thread -> no spills (R4's 64x64 tile hit the 255 clamp).
// k-pair-permuted smem layout so each fragment pair (k, k+4) is one LDS.64.
//   kp(k) = (k>>3)*8 + (k&3)*2 + ((k>>2)&1)
// Row stride 24 words -> conflict-free fragment loads per half-warp phase.
// MODE 0: C = acc
// MODE 1: C = gelu(acc + bias)
// MODE 2: C = resid_bchw + gamma[n]*(acc + bias)
// MODE 3: C = resid_row  + gamma[n]*(acc + bias)   (in-place safe)
// MODE 4: out_bchw = resid_row + gamma[n]*(acc + bias)
// ---------------------------------------------------------------------------
#define BM 128
#define BN 192
#define BK 16
#define SSTR 24                      // word stride per row
#define A_WORDS (BM * SSTR)          // 3072 per buffer
#define B_WORDS (BN * SSTR)          // 4608 per buffer
#define SMEM_WORDS (2 * A_WORDS + 2 * B_WORDS)   // 15360 words = 61440 B

__device__ __forceinline__ uint32_t f2tf32(float x) {
    uint32_t r;
    asm("cvt.rna.tf32.f32 %0, %1;" : "=r"(r) : "f"(x));
    return r;
}

__device__ __forceinline__ int kperm(int k) {
    return ((k >> 3) << 3) + ((k & 3) << 1) + ((k >> 2) & 1);
}

template<int MODE>
__global__ __launch_bounds__(256, 1)
void gemm_tf32_kernel(const float* __restrict__ A, const float* __restrict__ W,
                      float* __restrict__ Cout, int M, int N, int K,
                      const float* __restrict__ bias,
                      const float* __restrict__ gamma,
                      const float* __restrict__ resid) {
    extern __shared__ float sm[];
    float* Asm = sm;                       // [2][BM][SSTR]
    float* Bsm = sm + 2 * A_WORDS;         // [2][BN][SSTR]

    const int n0 = blockIdx.x * BN;
    const int m0 = blockIdx.y * BM;
    const int tid  = threadIdx.x;
    const int lane = tid & 31;
    const int wid  = tid >> 5;       // 0..7
    const int wm   = wid & 1;        // m-warp: 0..1  (64 rows each)
    const int wn   = wid >> 1;       // n-warp: 0..3  (48 cols each)

    // staging indices (256 threads)
    const int sRow = tid >> 2;       // 0..63
    const int sC4  = tid & 3;        // k quad
    const int kpBase[4] = { kperm(sC4*4+0), kperm(sC4*4+1), kperm(sC4*4+2), kperm(sC4*4+3) };

    float4 aR[2], bR[3];

    float acc[4][6][4];
#pragma unroll
    for (int i = 0; i < 4; i++)
#pragma unroll
        for (int j = 0; j < 6; j++)
#pragma unroll
            for (int q = 0; q < 4; q++) acc[i][j][q] = 0.f;

    const int nK = K / BK;

    // ---- prefetch chunk 0 ----
    {
#pragma unroll
        for (int it = 0; it < 2; it++) {
            int row = sRow + it * 64;
            aR[it] = *(const float4*)(A + (size_t)(m0 + row) * K + sC4 * 4);
        }
#pragma unroll
        for (int it = 0; it < 3; it++) {
            int row = sRow + it * 64;
            bR[it] = *(const float4*)(W + (size_t)(n0 + row) * K + sC4 * 4);
        }
    }

    int buf = 0;
    // ---- store chunk 0 ----
    {
#pragma unroll
        for (int it = 0; it < 2; it++) {
            int row = sRow + it * 64;
            float vv[4] = {aR[it].x, aR[it].y, aR[it].z, aR[it].w};
            float* dst = Asm + row * SSTR;
#pragma unroll
            for (int q = 0; q < 4; q++) dst[kpBase[q]] = __uint_as_float(f2tf32(vv[q]));
        }
#pragma unroll
        for (int it = 0; it < 3; it++) {
            int row = sRow + it * 64;
            float vv[4] = {bR[it].x, bR[it].y, bR[it].z, bR[it].w};
            float* dst = Bsm + row * SSTR;
#pragma unroll
            for (int q = 0; q < 4; q++) dst[kpBase[q]] = __uint_as_float(f2tf32(vv[q]));
        }
    }
    __syncthreads();

    const int fr = lane >> 2;          // 0..7
    const int fc = (lane & 3) << 1;    // 0,2,4,6

    for (int kt = 0; kt < nK; kt++) {
        // prefetch next chunk
        if (kt + 1 < nK) {
            int k0 = (kt + 1) * BK;
#pragma unroll
            for (int it = 0; it < 2; it++) {
                int row = sRow + it * 64;
                aR[it] = *(const float4*)(A + (size_t)(m0 + row) * K + k0 + sC4 * 4);
            }
#pragma unroll
            for (int it = 0; it < 3; it++) {
                int row = sRow + it * 64;
                bR[it] = *(const float4*)(W + (size_t)(n0 + row) * K + k0 + sC4 * 4);
            }
        }

        const float* Ab = Asm + buf * A_WORDS;
        const float* Bb = Bsm + buf * B_WORDS;

#pragma unroll
        for (int g = 0; g < 2; g++) {
            float2 aF[4][2];
#pragma unroll
            for (int i = 0; i < 4; i++) {
                int r = wm * 64 + i * 16 + fr;
                aF[i][0] = *(const float2*)(Ab + r * SSTR + g * 8 + fc);
                aF[i][1] = *(const float2*)(Ab + (r + 8) * SSTR + g * 8 + fc);
            }
            float2 bF[6];
#pragma unroll
            for (int j = 0; j < 6; j++) {
                int c = wn * 48 + j * 8 + fr;
                bF[j] = *(const float2*)(Bb + c * SSTR + g * 8 + fc);
            }
#pragma unroll
            for (int i = 0; i < 4; i++)
#pragma unroll
                for (int j = 0; j < 6; j++) {
                    asm volatile(
                        "mma.sync.aligned.m16n8k8.row.col.f32.tf32.tf32.f32 "
                        "{%0,%1,%2,%3},{%4,%5,%6,%7},{%8,%9},{%0,%1,%2,%3};"
                        : "+f"(acc[i][j][0]), "+f"(acc[i][j][1]),
                          "+f"(acc[i][j][2]), "+f"(acc[i][j][3])
                        : "r"(__float_as_uint(aF[i][0].x)), "r"(__float_as_uint(aF[i][1].x)),
                          "r"(__float_as_uint(aF[i][0].y)), "r"(__float_as_uint(aF[i][1].y)),
                          "r"(__float_as_uint(bF[j].x)),    "r"(__float_as_uint(bF[j].y)));
                }
        }

        // store next chunk into other buffer
        if (kt + 1 < nK) {
            float* Ad = Asm + (buf ^ 1) * A_WORDS;
            float* Bd = Bsm + (buf ^ 1) * B_WORDS;
#pragma unroll
            for (int it = 0; it < 2; it++) {
                int row = sRow + it * 64;
                float vv[4] = {aR[it].x, aR[it].y, aR[it].z, aR[it].w};
                float* dst = Ad + row * SSTR;
#pragma unroll
                for (int q = 0; q < 4; q++) dst[kpBase[q]] = __uint_as_float(f2tf32(vv[q]));
            }
#pragma unroll
            for (int it = 0; it < 3; it++) {
                int row = sRow + it * 64;
                float vv[4] = {bR[it].x, bR[it].y, bR[it].z, bR[it].w};
                float* dst = Bd + row * SSTR;
#pragma unroll
                for (int q = 0; q < 4; q++) dst[kpBase[q]] = __uint_as_float(f2tf32(vv[q]));
            }
            __syncthreads();
            buf ^= 1;
        }
    }

    // ---- epilogue ----
    const int rq = lane >> 2;
    const int cq = (lane & 3) * 2;
#pragma unroll
    for (int i = 0; i < 4; i++) {
#pragma unroll
        for (int j = 0; j < 6; j++) {
#pragma unroll
            for (int half = 0; half < 2; half++) {
#pragma unroll
                for (int cc = 0; cc < 2; cc++) {
                    int m = m0 + wm * 64 + i * 16 + rq + half * 8;
                    int n = n0 + wn * 48 + j * 8 + cq + cc;
                    float v = acc[i][j][half * 2 + cc];
                    if (MODE == 0) {
                        Cout[(size_t)m * N + n] = v;
                    } else if (MODE == 1) {
                        v += bias[n];
                        v = 0.5f * v * (1.0f + erff(v * 0.70710678118654752f));
                        Cout[(size_t)m * N + n] = v;
                    } else if (MODE == 2) {
                        int bb_ = m >> 14, l = m & (HW - 1);
                        float r = resid[((size_t)(bb_ * CH + n) << 14) + l];
                        Cout[(size_t)m * N + n] = r + gamma[n] * (v + bias[n]);
                    } else if (MODE == 3) {
                        float r = resid[(size_t)m * N + n];
                        Cout[(size_t)m * N + n] = r + gamma[n] * (v + bias[n]);
                    } else { // MODE 4
                        int bb_ = m >> 14, l = m & (HW - 1);
                        float r = resid[(size_t)m * N + n];
                        Cout[((size_t)(bb_ * CH + n) << 14) + l] = r + gamma[n] * (v + bias[n]);
                    }
                }
            }
        }
    }
}

// ---------------------------------------------------------------------------
// Window attention
// ---------------------------------------------------------------------------
__global__ __launch_bounds__(64)
void win_attn_kernel(const float* __restrict__ qkv,
                     const float* __restrict__ table,
                     float* __restrict__ out) {
    int h   = blockIdx.x & 7;
    int wid = blockIdx.x >> 3;
    int b   = wid >> 8;
    int rem = wid & 255;
    int wy  = rem >> 4, wx = rem & 15;

    int i  = threadIdx.x;
    int iy = i >> 3, ix = i & 7;
    int t  = (b << 14) + ((wy * 8 + iy) << 7) + wx * 8 + ix;

    __shared__ float ks[64][24];
    __shared__ float vs[64][24];
    __shared__ float bt[225];
    for (int p = i; p < 225; p += 64) bt[p] = table[p * NH + h];

    const float* row = qkv + (size_t)t * (3 * CH) + h * HD;
    float q[24];
#pragma unroll
    for (int d = 0; d < HD; d++) {
        q[d]     = row[d];
        ks[i][d] = row[CH + d];
        vs[i][d] = row[2 * CH + d];
    }
    __syncthreads();

    const float scale = 0.20412414523193154f;
    float sc[64];
    float mx = -1e30f;
#pragma unroll 4
    for (int j = 0; j < 64; j++) {
        int jy = j >> 3, jx = j & 7;
        float dot = 0.f;
#pragma unroll
        for (int d = 0; d < HD; d++) dot += q[d] * ks[j][d];
        dot = dot * scale + bt[(iy - jy + 7) * 15 + (ix - jx + 7)];
        sc[j] = dot;
        mx = fmaxf(mx, dot);
    }
    float sum = 0.f;
#pragma unroll 4
    for (int j = 0; j < 64; j++) { sc[j] = __expf(sc[j] - mx); sum += sc[j]; }
    float inv = 1.f / sum;

    float accum[24];
#pragma unroll
    for (int d = 0; d < HD; d++) accum[d] = 0.f;
#pragma unroll 2
    for (int j = 0; j < 64; j++) {
        float p = sc[j];
#pragma unroll
        for (int d = 0; d < HD; d++) accum[d] += p * vs[j][d];
    }
    float* op = out + (size_t)t * CH + h * HD;
#pragma unroll
    for (int d = 0; d < HD; d++) op[d] = accum[d] * inv;
}

// ---------------------------------------------------------------------------
// Channel attention
// ---------------------------------------------------------------------------
__global__ __launch_bounds__(576)
void ca_gram_kernel(const float* __restrict__ qkv, float* __restrict__ gram) {
    int bh = blockIdx.x;
    int b = bh >> 3, h = bh & 7;
    int tid = threadIdx.x;
    int d = tid / 24, e = tid - d * 24;

    __shared__ float qs[64][24];
    __shared__ float ks[64][24];

    const int chunk = HW / 16;
    int l0 = blockIdx.y * chunk;
    float accum = 0.f;
    for (int tile = 0; tile < chunk; tile += 64) {
        for (int p = tid; p < 64 * 24; p += 576) {
            int tok = p / 24, dd = p - tok * 24;
            size_t base = (size_t)((b << 14) + l0 + tile + tok) * (3 * CH) + h * HD + dd;
            qs[tok][dd] = qkv[base];
            ks[tok][dd] = qkv[base + CH];
        }
        __syncthreads();
#pragma unroll 8
        for (int tok = 0; tok < 64; tok++) accum += qs[tok][d] * ks[tok][e];
        __syncthreads();
    }
    atomicAdd(&gram[bh * (HD * HD) + tid], accum);
}

__global__ void zero_gram_kernel(float* __restrict__ gram) {
    int i = blockIdx.x * blockDim.x + threadIdx.x;
    if (i < NH * BATCH * HD * HD) gram[i] = 0.f;
}

__global__ void ca_softmax_kernel(const float* __restrict__ gram, float* __restrict__ A) {
    int bh = blockIdx.x;
    int d = threadIdx.x;
    if (d >= HD) return;
    const float scale = 0.20412414523193154f;
    float r[24];
    float mx = -1e30f;
#pragma unroll
    for (int e = 0; e < HD; e++) {
        r[e] = gram[bh * (HD * HD) + d * HD + e] * scale;
        mx = fmaxf(mx, r[e]);
    }
    float sum = 0.f;
#pragma unroll
    for (int e = 0; e < HD; e++) { r[e] = __expf(r[e] - mx); sum += r[e]; }
    float inv = 1.f / sum;
#pragma unroll
    for (int e = 0; e < HD; e++) A[bh * (HD * HD) + d * HD + e] = r[e] * inv;
}

__global__ __launch_bounds__(256)
void ca_out_kernel(const float* __restrict__ qkv, const float* __restrict__ A,
                   float* __restrict__ out) {
    int b  = blockIdx.x;
    int l0 = blockIdx.y * 32;
    int tid = threadIdx.x;
    __shared__ float vs[32][192];
    for (int p = tid; p < 32 * 192; p += 256) {
        int tok = p / 192, c = p - tok * 192;
        vs[tok][c] = qkv[(size_t)((b << 14) + l0 + tok) * (3 * CH) + 2 * CH + c];
    }
    __syncthreads();
    int tok = tid >> 3;
    int h   = tid & 7;
    int t   = (b << 14) + l0 + tok;
    const float* Ah = A + (b * 8 + h) * (HD * HD);
    float* op = out + (size_t)t * CH + h * HD;
#pragma unroll
    for (int d = 0; d < HD; d++) {
        float s = 0.f;
#pragma unroll
        for (int e = 0; e < HD; e++) s += Ah[d * HD + e] * vs[tok][h * HD + e];
        op[d] = s;
    }
}

// ---------------------------------------------------------------------------
// Launch
// ---------------------------------------------------------------------------
extern "C" void kernel_launch(void* const* d_in, const int* in_sizes, int n_in,
                              void* d_out, int out_size) {
    const float* x          = (const float*)d_in[0];
    const float* sa_norm_w  = (const float*)d_in[1];
    const float* sa_norm_b  = (const float*)d_in[2];
    const float* sa_qkv_w   = (const float*)d_in[3];
    const float* sa_proj_w  = (const float*)d_in[4];
    const float* sa_proj_b  = (const float*)d_in[5];
    const float* sa_bias_t  = (const float*)d_in[6];
    const float* ca_norm_w  = (const float*)d_in[7];
    const float* ca_norm_b  = (const float*)d_in[8];
    const float* ca_qkv_w   = (const float*)d_in[9];
    const float* ca_proj_w  = (const float*)d_in[10];
    const float* ca_proj_b  = (const float*)d_in[11];
    const float* ffn_norm_w = (const float*)d_in[12];
    const float* ffn_norm_b = (const float*)d_in[13];
    const float* ffn_w1     = (const float*)d_in[14];
    const float* ffn_b1     = (const float*)d_in[15];
    const float* ffn_w2     = (const float*)d_in[16];
    const float* ffn_w2b    = (const float*)d_in[17];
    const float* gamma1     = (const float*)d_in[18];
    const float* gamma2     = (const float*)d_in[19];
    const float* gamma3     = (const float*)d_in[20];
    float* out = (float*)d_out;

    float *xn, *qkv, *att, *x1, *h1, *gram, *Amat;
    cudaGetSymbolAddress((void**)&xn,   g_xn);
    cudaGetSymbolAddress((void**)&qkv,  g_qkv);
    cudaGetSymbolAddress((void**)&att,  g_att);
    cudaGetSymbolAddress((void**)&x1,   g_x1);
    cudaGetSymbolAddress((void**)&h1,   g_h1);
    cudaGetSymbolAddress((void**)&gram, g_gram);
    cudaGetSymbolAddress((void**)&Amat, g_A);

    // Opt-in to 60KB dynamic smem (idempotent, no static guards per harness rules)
    const int smemB = SMEM_WORDS * 4;  // 61440
    cudaFuncSetAttribute(gemm_tf32_kernel<0>, cudaFuncAttributeMaxDynamicSharedMemorySize, smemB);
    cudaFuncSetAttribute(gemm_tf32_kernel<1>, cudaFuncAttributeMaxDynamicSharedMemorySize, smemB);
    cudaFuncSetAttribute(gemm_tf32_kernel<2>, cudaFuncAttributeMaxDynamicSharedMemorySize, smemB);
    cudaFuncSetAttribute(gemm_tf32_kernel<3>, cudaFuncAttributeMaxDynamicSharedMemorySize, smemB);
    cudaFuncSetAttribute(gemm_tf32_kernel<4>, cudaFuncAttributeMaxDynamicSharedMemorySize, smemB);

    const int lnBlocks = TOK / 8;

    // ---- stage 1: window attention ----
    ln_bchw_kernel<<<lnBlocks, 256>>>(x, sa_norm_w, sa_norm_b, xn);
    gemm_tf32_kernel<0><<<dim3(3 * CH / BN, TOK / BM), 256, smemB>>>(
        xn, sa_qkv_w, qkv, TOK, 3 * CH, CH, nullptr, nullptr, nullptr);
    win_attn_kernel<<<NWIN * NH, 64>>>(qkv, sa_bias_t, att);
    gemm_tf32_kernel<2><<<dim3(CH / BN, TOK / BM), 256, smemB>>>(
        att, sa_proj_w, x1, TOK, CH, CH, sa_proj_b, gamma1, x);

    // ---- stage 2: channel attention ----
    ln_row_kernel<<<lnBlocks, 256>>>(x1, ca_norm_w, ca_norm_b, xn);
    gemm_tf32_kernel<0><<<dim3(3 * CH / BN, TOK / BM), 256, smemB>>>(
        xn, ca_qkv_w, qkv, TOK, 3 * CH, CH, nullptr, nullptr, nullptr);
    zero_gram_kernel<<<(NH * BATCH * HD * HD + 255) / 256, 256>>>(gram);
    ca_gram_kernel<<<dim3(NH * BATCH, 16), 576>>>(qkv, gram);
    ca_softmax_kernel<<<NH * BATCH, 32>>>(gram, Amat);
    ca_out_kernel<<<dim3(BATCH, HW / 32), 256>>>(qkv, Amat, att);
    gemm_tf32_kernel<3><<<dim3(CH / BN, TOK / BM), 256, smemB>>>(
        att, ca_proj_w, x1, TOK, CH, CH, ca_proj_b, gamma2, x1);

    // ---- stage 3: gated FFN ----
    ln_row_kernel<<<lnBlocks, 256>>>(x1, ffn_norm_w, ffn_norm_b, xn);
    gemm_tf32_kernel<1><<<dim3(FFN / BN, TOK / BM), 256, smemB>>>(
        xn, ffn_w1, h1, TOK, FFN, CH, ffn_b1, nullptr, nullptr);
    gemm_tf32_kernel<4><<<dim3(CH / BN, TOK / BM), 256, smemB>>>(
        h1, ffn_w2, out, TOK, CH, FFN, ffn_w2b, gamma3, x1);
}

// round 7
// speedup vs baseline: 1.7144x; 1.0562x over previous
#include <cuda_runtime.h>
#include <cuda_bf16.h>
#include <math.h>
#include <stdint.h>

// ---------------------------------------------------------------------------
// Problem constants
// ---------------------------------------------------------------------------
#define BATCH 8
#define CH    192
#define HH    128
#define WW    128
#define HW    (HH*WW)            // 16384
#define TOK   (BATCH*HW)         // 131072
#define NH    8
#define HD    24
#define WS    8
#define FFN   768
#define NWIN  (BATCH*16*16)      // 2048 windows

// ---------------------------------------------------------------------------
// Scratch (device globals; no runtime allocation allowed)
// ---------------------------------------------------------------------------
__device__ float g_xn [TOK*CH];
__device__ float g_qkv[TOK*3*CH];
__device__ float g_att[TOK*CH];
__device__ float g_x1 [TOK*CH];
__device__ float g_h1 [TOK*FFN];
__device__ float g_gram[NH*BATCH*HD*HD];
__device__ float g_A   [NH*BATCH*HD*HD];

__device__ __forceinline__ uint32_t smem_u32(const void* p) {
    return (uint32_t)__cvta_generic_to_shared(p);
}

// ---------------------------------------------------------------------------
// LayerNorms
// ---------------------------------------------------------------------------
__global__ void ln_bchw_kernel(const float* __restrict__ x,
                               const float* __restrict__ w,
                               const float* __restrict__ bb,
                               float* __restrict__ out) {
    int gwarp = (blockIdx.x * blockDim.x + threadIdx.x) >> 5;
    int lane  = threadIdx.x & 31;
    if (gwarp >= TOK) return;
    int b = gwarp >> 14;
    int l = gwarp & (HW - 1);
    const float* xp = x + ((size_t)b * CH << 14) + l;
    float v[6];
    float s = 0.f;
#pragma unroll
    for (int j = 0; j < 6; j++) {
        int c = lane + 32 * j;
        v[j] = xp[(size_t)c << 14];
        s += v[j];
    }
#pragma unroll
    for (int o = 16; o > 0; o >>= 1) s += __shfl_xor_sync(0xffffffffu, s, o);
    float mean = s * (1.f / CH);
    float s2 = 0.f;
#pragma unroll
    for (int j = 0; j < 6; j++) { float d = v[j] - mean; s2 += d * d; }
#pragma unroll
    for (int o = 16; o > 0; o >>= 1) s2 += __shfl_xor_sync(0xffffffffu, s2, o);
    float rstd = rsqrtf(s2 * (1.f / CH) + 1e-5f);
    float* op = out + (size_t)gwarp * CH;
#pragma unroll
    for (int j = 0; j < 6; j++) {
        int c = lane + 32 * j;
        op[c] = (v[j] - mean) * rstd * w[c] + bb[c];
    }
}

__global__ void ln_row_kernel(const float* __restrict__ x,
                              const float* __restrict__ w,
                              const float* __restrict__ bb,
                              float* __restrict__ out) {
    int gwarp = (blockIdx.x * blockDim.x + threadIdx.x) >> 5;
    int lane  = threadIdx.x & 31;
    if (gwarp >= TOK) return;
    const float* xp = x + (size_t)gwarp * CH;
    float v[6];
    float s = 0.f;
#pragma unroll
    for (int j = 0; j < 6; j++) { v[j] = xp[lane + 32 * j]; s += v[j]; }
#pragma unroll
    for (int o = 16; o > 0; o >>= 1) s += __shfl_xor_sync(0xffffffffu, s, o);
    float mean = s * (1.f / CH);
    float s2 = 0.f;
#pragma unroll
    for (int j = 0; j < 6; j++) { float d = v[j] - mean; s2 += d * d; }
#pragma unroll
    for (int o = 16; o > 0; o >>= 1) s2 += __shfl_xor_sync(0xffffffffu, s2, o);
    float rstd = rsqrtf(s2 * (1.f / CH) + 1e-5f);
    float* op = out + (size_t)gwarp * CH;
#pragma unroll
    for (int j = 0; j < 6; j++) {
        int c = lane + 32 * j;
        op[c] = (v[j] - mean) * rstd * w[c] + bb[c];
    }
}

// ---------------------------------------------------------------------------
// TF32 tensor-core GEMM via mma.sync + cp.async 4-stage pipeline.
// C[M,N] = A[M,K] @ W[N,K]^T.
// CTA tile 128x96x16; 8 warps (4m x 2n), warp tile 32x48 (2x6 m16n8k8).
// Inputs stay fp32 in smem; mma.sync.tf32 truncates mantissa in HW.
// Smem: row = 16 floats (64B) as 4 x 16B chunks, chunk swizzled by (c ^ (r&3)).
// MODE 0: C = acc
// MODE 1: C = gelu(acc + bias)
// MODE 2: C = resid_bchw + gamma[n]*(acc + bias)
// MODE 3: C = resid_row  + gamma[n]*(acc + bias)   (in-place safe)
// MODE 4: out_bchw = resid_row + gamma[n]*(acc + bias)
// ---------------------------------------------------------------------------
#define BM 128
#define BN 96
#define BK 16
#define STAGES 4
#define A_ST_B (BM * 64)                 // 8192 bytes per stage
#define B_ST_B (BN * 64)                 // 6144 bytes per stage
#define ST_B   (A_ST_B + B_ST_B)         // 14336
#define GEMM_SMEM (STAGES * ST_B)        // 57344

__device__ __forceinline__ void cp16(uint32_t dst, const void* src) {
    asm volatile("cp.async.cg.shared.global [%0], [%1], 16;" :: "r"(dst), "l"(src) : "memory");
}

template<int MODE>
__global__ __launch_bounds__(256, 2)
void gemm_tf32_kernel(const float* __restrict__ A, const float* __restrict__ W,
                      float* __restrict__ Cout, int M, int N, int K,
                      const float* __restrict__ bias,
                      const float* __restrict__ gamma,
                      const float* __restrict__ resid) {
    extern __shared__ char sm[];
    const uint32_t smBase = smem_u32(sm);

    const int n0 = blockIdx.x * BN;
    const int m0 = blockIdx.y * BM;
    const int tid  = threadIdx.x;
    const int lane = tid & 31;
    const int wid  = tid >> 5;       // 0..7
    const int wm   = wid & 3;        // 0..3 -> 32 rows each
    const int wn   = wid >> 2;       // 0..1 -> 48 cols each

    float acc[2][6][4];
#pragma unroll
    for (int i = 0; i < 2; i++)
#pragma unroll
        for (int j = 0; j < 6; j++)
#pragma unroll
            for (int q = 0; q < 4; q++) acc[i][j][q] = 0.f;

    const int nK = K / BK;

    // per-thread load coords (16B chunks): A has 512 chunks, B has 384.
    const int ldRow = tid >> 2;          // 0..63
    const int ldC   = tid & 3;           // chunk col 0..3

    auto load_stage = [&](int chunk, int st) {
        const int k0 = chunk * BK;
        const uint32_t aB = smBase + st * ST_B;
        const uint32_t bB = aB + A_ST_B;
        // A: rows ldRow, ldRow+64
#pragma unroll
        for (int it = 0; it < 2; it++) {
            int r = ldRow + it * 64;
            uint32_t dst = aB + r * 64 + ((ldC ^ (r & 3)) << 4);
            cp16(dst, A + (size_t)(m0 + r) * K + k0 + ldC * 4);
        }
        // B: rows ldRow (<96), second half: rows 64..95 from tids 0..127
        {
            int r = ldRow;
            uint32_t dst = bB + r * 64 + ((ldC ^ (r & 3)) << 4);
            cp16(dst, W + (size_t)(n0 + r) * K + k0 + ldC * 4);
        }
        if (tid < 128) {
            int r = 64 + ldRow;
            uint32_t dst = bB + r * 64 + ((ldC ^ (r & 3)) << 4);
            cp16(dst, W + (size_t)(n0 + r) * K + k0 + ldC * 4);
        }
        asm volatile("cp.async.commit_group;" ::: "memory");
    };

    // prologue: stages 0..2
    load_stage(0, 0);
    load_stage(1, 1);
    load_stage(2, 2);

    const int fr  = lane >> 2;     // 0..7
    const int fq  = lane & 3;      // 0..3
    const uint32_t foff = fq << 2; // byte offset within 16B chunk

    for (int kt = 0; kt < nK; kt++) {
        asm volatile("cp.async.wait_group %0;" :: "n"(STAGES - 2) : "memory");
        __syncthreads();

        if (kt + STAGES - 1 < nK) load_stage(kt + STAGES - 1, (kt + STAGES - 1) & (STAGES - 1));
        else asm volatile("cp.async.commit_group;" ::: "memory");

        const int st = kt & (STAGES - 1);
        const uint32_t aB = smBase + st * ST_B;
        const uint32_t bB = aB + A_ST_B;

#pragma unroll
        for (int g = 0; g < 2; g++) {
            const int ch0 = g * 2, ch1 = g * 2 + 1;
            uint32_t a[2][4];
#pragma unroll
            for (int i = 0; i < 2; i++) {
                int r0 = wm * 32 + i * 16 + fr;
                int r1 = r0 + 8;
                uint32_t a00 = aB + r0 * 64 + ((ch0 ^ (r0 & 3)) << 4) + foff;
                uint32_t a01 = aB + r1 * 64 + ((ch0 ^ (r1 & 3)) << 4) + foff;
                uint32_t a10 = aB + r0 * 64 + ((ch1 ^ (r0 & 3)) << 4) + foff;
                uint32_t a11 = aB + r1 * 64 + ((ch1 ^ (r1 & 3)) << 4) + foff;
                asm volatile("ld.shared.b32 %0, [%1];" : "=r"(a[i][0]) : "r"(a00));
                asm volatile("ld.shared.b32 %0, [%1];" : "=r"(a[i][1]) : "r"(a01));
                asm volatile("ld.shared.b32 %0, [%1];" : "=r"(a[i][2]) : "r"(a10));
                asm volatile("ld.shared.b32 %0, [%1];" : "=r"(a[i][3]) : "r"(a11));
            }
            uint32_t b[6][2];
#pragma unroll
            for (int j = 0; j < 6; j++) {
                int c = wn * 48 + j * 8 + fr;
                uint32_t b0 = bB + c * 64 + ((ch0 ^ (c & 3)) << 4) + foff;
                uint32_t b1 = bB + c * 64 + ((ch1 ^ (c & 3)) << 4) + foff;
                asm volatile("ld.shared.b32 %0, [%1];" : "=r"(b[j][0]) : "r"(b0));
                asm volatile("ld.shared.b32 %0, [%1];" : "=r"(b[j][1]) : "r"(b1));
            }
#pragma unroll
            for (int i = 0; i < 2; i++)
#pragma unroll
                for (int j = 0; j < 6; j++) {
                    asm volatile(
                        "mma.sync.aligned.m16n8k8.row.col.f32.tf32.tf32.f32 "
                        "{%0,%1,%2,%3},{%4,%5,%6,%7},{%8,%9},{%0,%1,%2,%3};"
                        : "+f"(acc[i][j][0]), "+f"(acc[i][j][1]),
                          "+f"(acc[i][j][2]), "+f"(acc[i][j][3])
                        : "r"(a[i][0]), "r"(a[i][1]), "r"(a[i][2]), "r"(a[i][3]),
                          "r"(b[j][0]), "r"(b[j][1]));
                }
        }
        __syncthreads();
    }

    // ---- epilogue ----
    const int rq = lane >> 2;
    const int cq = (lane & 3) * 2;
#pragma unroll
    for (int i = 0; i < 2; i++) {
#pragma unroll
        for (int j = 0; j < 6; j++) {
#pragma unroll
            for (int half = 0; half < 2; half++) {
#pragma unroll
                for (int cc = 0; cc < 2; cc++) {
                    int m = m0 + wm * 32 + i * 16 + rq + half * 8;
                    int n = n0 + wn * 48 + j * 8 + cq + cc;
                    float v = acc[i][j][half * 2 + cc];
                    if (MODE == 0) {
                        Cout[(size_t)m * N + n] = v;
                    } else if (MODE == 1) {
                        v += bias[n];
                        v = 0.5f * v * (1.0f + erff(v * 0.70710678118654752f));
                        Cout[(size_t)m * N + n] = v;
                    } else if (MODE == 2) {
                        int bb_ = m >> 14, l = m & (HW - 1);
                        float r = resid[((size_t)(bb_ * CH + n) << 14) + l];
                        Cout[(size_t)m * N + n] = r + gamma[n] * (v + bias[n]);
                    } else if (MODE == 3) {
                        float r = resid[(size_t)m * N + n];
                        Cout[(size_t)m * N + n] = r + gamma[n] * (v + bias[n]);
                    } else { // MODE 4
                        int bb_ = m >> 14, l = m & (HW - 1);
                        float r = resid[(size_t)m * N + n];
                        Cout[((size_t)(bb_ * CH + n) << 14) + l] = r + gamma[n] * (v + bias[n]);
                    }
                }
            }
        }
    }
}

// ---------------------------------------------------------------------------
// Window attention
// ---------------------------------------------------------------------------
__global__ __launch_bounds__(64)
void win_attn_kernel(const float* __restrict__ qkv,
                     const float* __restrict__ table,
                     float* __restrict__ out) {
    int h   = blockIdx.x & 7;
    int wid = blockIdx.x >> 3;
    int b   = wid >> 8;
    int rem = wid & 255;
    int wy  = rem >> 4, wx = rem & 15;

    int i  = threadIdx.x;
    int iy = i >> 3, ix = i & 7;
    int t  = (b << 14) + ((wy * 8 + iy) << 7) + wx * 8 + ix;

    __shared__ float ks[64][24];
    __shared__ float vs[64][24];
    __shared__ float bt[225];
    for (int p = i; p < 225; p += 64) bt[p] = table[p * NH + h];

    const float* row = qkv + (size_t)t * (3 * CH) + h * HD;
    float q[24];
#pragma unroll
    for (int d = 0; d < HD; d++) {
        q[d]     = row[d];
        ks[i][d] = row[CH + d];
        vs[i][d] = row[2 * CH + d];
    }
    __syncthreads();

    const float scale = 0.20412414523193154f;
    float sc[64];
    float mx = -1e30f;
#pragma unroll 4
    for (int j = 0; j < 64; j++) {
        int jy = j >> 3, jx = j & 7;
        float dot = 0.f;
#pragma unroll
        for (int d = 0; d < HD; d++) dot += q[d] * ks[j][d];
        dot = dot * scale + bt[(iy - jy + 7) * 15 + (ix - jx + 7)];
        sc[j] = dot;
        mx = fmaxf(mx, dot);
    }
    float sum = 0.f;
#pragma unroll 4
    for (int j = 0; j < 64; j++) { sc[j] = __expf(sc[j] - mx); sum += sc[j]; }
    float inv = 1.f / sum;

    float accum[24];
#pragma unroll
    for (int d = 0; d < HD; d++) accum[d] = 0.f;
#pragma unroll 2
    for (int j = 0; j < 64; j++) {
        float p = sc[j];
#pragma unroll
        for (int d = 0; d < HD; d++) accum[d] += p * vs[j][d];
    }
    float* op = out + (size_t)t * CH + h * HD;
#pragma unroll
    for (int d = 0; d < HD; d++) op[d] = accum[d] * inv;
}

// ---------------------------------------------------------------------------
// Channel attention
// ---------------------------------------------------------------------------
__global__ __launch_bounds__(576)
void ca_gram_kernel(const float* __restrict__ qkv, float* __restrict__ gram) {
    int bh = blockIdx.x;
    int b = bh >> 3, h = bh & 7;
    int tid = threadIdx.x;
    int d = tid / 24, e = tid - d * 24;

    __shared__ float qs[64][24];
    __shared__ float ks[64][24];

    const int chunk = HW / 16;
    int l0 = blockIdx.y * chunk;
    float accum = 0.f;
    for (int tile = 0; tile < chunk; tile += 64) {
        for (int p = tid; p < 64 * 24; p += 576) {
            int tok = p / 24, dd = p - tok * 24;
            size_t base = (size_t)((b << 14) + l0 + tile + tok) * (3 * CH) + h * HD + dd;
            qs[tok][dd] = qkv[base];
            ks[tok][dd] = qkv[base + CH];
        }
        __syncthreads();
#pragma unroll 8
        for (int tok = 0; tok < 64; tok++) accum += qs[tok][d] * ks[tok][e];
        __syncthreads();
    }
    atomicAdd(&gram[bh * (HD * HD) + tid], accum);
}

__global__ void zero_gram_kernel(float* __restrict__ gram) {
    int i = blockIdx.x * blockDim.x + threadIdx.x;
    if (i < NH * BATCH * HD * HD) gram[i] = 0.f;
}

__global__ void ca_softmax_kernel(const float* __restrict__ gram, float* __restrict__ A) {
    int bh = blockIdx.x;
    int d = threadIdx.x;
    if (d >= HD) return;
    const float scale = 0.20412414523193154f;
    float r[24];
    float mx = -1e30f;
#pragma unroll
    for (int e = 0; e < HD; e++) {
        r[e] = gram[bh * (HD * HD) + d * HD + e] * scale;
        mx = fmaxf(mx, r[e]);
    }
    float sum = 0.f;
#pragma unroll
    for (int e = 0; e < HD; e++) { r[e] = __expf(r[e] - mx); sum += r[e]; }
    float inv = 1.f / sum;
#pragma unroll
    for (int e = 0; e < HD; e++) A[bh * (HD * HD) + d * HD + e] = r[e] * inv;
}

__global__ __launch_bounds__(256)
void ca_out_kernel(const float* __restrict__ qkv, const float* __restrict__ A,
                   float* __restrict__ out) {
    int b  = blockIdx.x;
    int l0 = blockIdx.y * 32;
    int tid = threadIdx.x;
    __shared__ float vs[32][192];
    for (int p = tid; p < 32 * 192; p += 256) {
        int tok = p / 192, c = p - tok * 192;
        vs[tok][c] = qkv[(size_t)((b << 14) + l0 + tok) * (3 * CH) + 2 * CH + c];
    }
    __syncthreads();
    int tok = tid >> 3;
    int h   = tid & 7;
    int t   = (b << 14) + l0 + tok;
    const float* Ah = A + (b * 8 + h) * (HD * HD);
    float* op = out + (size_t)t * CH + h * HD;
#pragma unroll
    for (int d = 0; d < HD; d++) {
        float s = 0.f;
#pragma unroll
        for (int e = 0; e < HD; e++) s += Ah[d * HD + e] * vs[tok][h * HD + e];
        op[d] = s;
    }
}

// ---------------------------------------------------------------------------
// Launch
// ---------------------------------------------------------------------------
extern "C" void kernel_launch(void* const* d_in, const int* in_sizes, int n_in,
                              void* d_out, int out_size) {
    const float* x          = (const float*)d_in[0];
    const float* sa_norm_w  = (const float*)d_in[1];
    const float* sa_norm_b  = (const float*)d_in[2];
    const float* sa_qkv_w   = (const float*)d_in[3];
    const float* sa_proj_w  = (const float*)d_in[4];
    const float* sa_proj_b  = (const float*)d_in[5];
    const float* sa_bias_t  = (const float*)d_in[6];
    const float* ca_norm_w  = (const float*)d_in[7];
    const float* ca_norm_b  = (const float*)d_in[8];
    const float* ca_qkv_w   = (const float*)d_in[9];
    const float* ca_proj_w  = (const float*)d_in[10];
    const float* ca_proj_b  = (const float*)d_in[11];
    const float* ffn_norm_w = (const float*)d_in[12];
    const float* ffn_norm_b = (const float*)d_in[13];
    const float* ffn_w1     = (const float*)d_in[14];
    const float* ffn_b1     = (const float*)d_in[15];
    const float* ffn_w2     = (const float*)d_in[16];
    const float* ffn_w2b    = (const float*)d_in[17];
    const float* gamma1     = (const float*)d_in[18];
    const float* gamma2     = (const float*)d_in[19];
    const float* gamma3     = (const float*)d_in[20];
    float* out = (float*)d_out;

    float *xn, *qkv, *att, *x1, *h1, *gram, *Amat;
    cudaGetSymbolAddress((void**)&xn,   g_xn);
    cudaGetSymbolAddress((void**)&qkv,  g_qkv);
    cudaGetSymbolAddress((void**)&att,  g_att);
    cudaGetSymbolAddress((void**)&x1,   g_x1);
    cudaGetSymbolAddress((void**)&h1,   g_h1);
    cudaGetSymbolAddress((void**)&gram, g_gram);
    cudaGetSymbolAddress((void**)&Amat, g_A);

    const int smemB = GEMM_SMEM;  // 57344
    cudaFuncSetAttribute(gemm_tf32_kernel<0>, cudaFuncAttributeMaxDynamicSharedMemorySize, smemB);
    cudaFuncSetAttribute(gemm_tf32_kernel<1>, cudaFuncAttributeMaxDynamicSharedMemorySize, smemB);
    cudaFuncSetAttribute(gemm_tf32_kernel<2>, cudaFuncAttributeMaxDynamicSharedMemorySize, smemB);
    cudaFuncSetAttribute(gemm_tf32_kernel<3>, cudaFuncAttributeMaxDynamicSharedMemorySize, smemB);
    cudaFuncSetAttribute(gemm_tf32_kernel<4>, cudaFuncAttributeMaxDynamicSharedMemorySize, smemB);

    const int lnBlocks = TOK / 8;

    // ---- stage 1: window attention ----
    ln_bchw_kernel<<<lnBlocks, 256>>>(x, sa_norm_w, sa_norm_b, xn);
    gemm_tf32_kernel<0><<<dim3(3 * CH / BN, TOK / BM), 256, smemB>>>(
        xn, sa_qkv_w, qkv, TOK, 3 * CH, CH, nullptr, nullptr, nullptr);
    win_attn_kernel<<<NWIN * NH, 64>>>(qkv, sa_bias_t, att);
    gemm_tf32_kernel<2><<<dim3(CH / BN, TOK / BM), 256, smemB>>>(
        att, sa_proj_w, x1, TOK, CH, CH, sa_proj_b, gamma1, x);

    // ---- stage 2: channel attention ----
    ln_row_kernel<<<lnBlocks, 256>>>(x1, ca_norm_w, ca_norm_b, xn);
    gemm_tf32_kernel<0><<<dim3(3 * CH / BN, TOK / BM), 256, smemB>>>(
        xn, ca_qkv_w, qkv, TOK, 3 * CH, CH, nullptr, nullptr, nullptr);
    zero_gram_kernel<<<(NH * BATCH * HD * HD + 255) / 256, 256>>>(gram);
    ca_gram_kernel<<<dim3(NH * BATCH, 16), 576>>>(qkv, gram);
    ca_softmax_kernel<<<NH * BATCH, 32>>>(gram, Amat);
    ca_out_kernel<<<dim3(BATCH, HW / 32), 256>>>(qkv, Amat, att);
    gemm_tf32_kernel<3><<<dim3(CH / BN, TOK / BM), 256, smemB>>>(
        att, ca_proj_w, x1, TOK, CH, CH, ca_proj_b, gamma2, x1);

    // ---- stage 3: gated FFN ----
    ln_row_kernel<<<lnBlocks, 256>>>(x1, ffn_norm_w, ffn_norm_b, xn);
    gemm_tf32_kernel<1><<<dim3(FFN / BN, TOK / BM), 256, smemB>>>(
        xn, ffn_w1, h1, TOK, FFN, CH, ffn_b1, nullptr, nullptr);
    gemm_tf32_kernel<4><<<dim3(CH / BN, TOK / BM), 256, smemB>>>(
        h1, ffn_w2, out, TOK, CH, FFN, ffn_w2b, gamma3, x1);
}

// round 9
// speedup vs baseline: 2.2387x; 1.3058x over previous
#include <cuda_runtime.h>
#include <cuda_fp16.h>
#include <math.h>
#include <stdint.h>

// ---------------------------------------------------------------------------
// Problem constants
// ---------------------------------------------------------------------------
#define BATCH 8
#define CH    192
#define HH    128
#define WW    128
#define HW    (HH*WW)            // 16384
#define TOK   (BATCH*HW)         // 131072
#define NH    8
#define HD    24
#define WS    8
#define FFN   768
#define NWIN  (BATCH*16*16)      // 2048 windows

// ---------------------------------------------------------------------------
// Scratch (device globals; no runtime allocation allowed)
// ---------------------------------------------------------------------------
__device__ __half g_xn [TOK*CH];       // normalized activations (fp16)
__device__ __half g_qkv[TOK*3*CH];     // qkv (fp16)
__device__ __half g_att[TOK*CH];       // attention outputs (fp16)
__device__ __half g_h1 [TOK*FFN];      // FFN hidden (fp16)
__device__ float  g_x1 [TOK*CH];       // residual stream (fp32)
__device__ float  g_gram[NH*BATCH*HD*HD];
__device__ float  g_A   [NH*BATCH*HD*HD];
// packed fp16 weights: sa_qkv | sa_proj | ca_qkv | ca_proj | ffn_w1 | ffn_w2
#define W_SAQKV 0
#define W_SAPROJ (W_SAQKV + 3*CH*CH)       // 110592
#define W_CAQKV (W_SAPROJ + CH*CH)         // 147456
#define W_CAPROJ (W_CAQKV + 3*CH*CH)       // 258048
#define W_FFN1  (W_CAPROJ + CH*CH)         // 294912
#define W_FFN2  (W_FFN1 + FFN*CH)          // 442368
#define W_TOTAL (W_FFN2 + CH*FFN)          // 589824
__device__ __half g_wbuf[W_TOTAL];

__device__ __forceinline__ uint32_t smem_u32(const void* p) {
    return (uint32_t)__cvta_generic_to_shared(p);
}

// ---------------------------------------------------------------------------
// fp32 -> fp16 weight conversion (4 elems/thread)
// ---------------------------------------------------------------------------
__global__ void f2h_kernel(const float* __restrict__ in, __half* __restrict__ out, int n4) {
    int i = blockIdx.x * blockDim.x + threadIdx.x;
    if (i >= n4) return;
    float4 v = *(const float4*)(in + i * 4);
    __half2 a = __floats2half2_rn(v.x, v.y);
    __half2 b = __floats2half2_rn(v.z, v.w);
    *(__half2*)(out + i * 4)     = a;
    *(__half2*)(out + i * 4 + 2) = b;
}

// ---------------------------------------------------------------------------
// LayerNorms: fp32 in -> fp16 out
// ---------------------------------------------------------------------------
__global__ void ln_bchw_kernel(const float* __restrict__ x,
                               const float* __restrict__ w,
                               const float* __restrict__ bb,
                               __half* __restrict__ out) {
    int gwarp = (blockIdx.x * blockDim.x + threadIdx.x) >> 5;
    int lane  = threadIdx.x & 31;
    if (gwarp >= TOK) return;
    int b = gwarp >> 14;
    int l = gwarp & (HW - 1);
    const float* xp = x + ((size_t)b * CH << 14) + l;
    float v[6];
    float s = 0.f;
#pragma unroll
    for (int j = 0; j < 6; j++) {
        int c = lane + 32 * j;
        v[j] = xp[(size_t)c << 14];
        s += v[j];
    }
#pragma unroll
    for (int o = 16; o > 0; o >>= 1) s += __shfl_xor_sync(0xffffffffu, s, o);
    float mean = s * (1.f / CH);
    float s2 = 0.f;
#pragma unroll
    for (int j = 0; j < 6; j++) { float d = v[j] - mean; s2 += d * d; }
#pragma unroll
    for (int o = 16; o > 0; o >>= 1) s2 += __shfl_xor_sync(0xffffffffu, s2, o);
    float rstd = rsqrtf(s2 * (1.f / CH) + 1e-5f);
    __half* op = out + (size_t)gwarp * CH;
#pragma unroll
    for (int j = 0; j < 6; j++) {
        int c = lane + 32 * j;
        op[c] = __float2half((v[j] - mean) * rstd * w[c] + bb[c]);
    }
}

__global__ void ln_row_kernel(const float* __restrict__ x,
                              const float* __restrict__ w,
                              const float* __restrict__ bb,
                              __half* __restrict__ out) {
    int gwarp = (blockIdx.x * blockDim.x + threadIdx.x) >> 5;
    int lane  = threadIdx.x & 31;
    if (gwarp >= TOK) return;
    const float* xp = x + (size_t)gwarp * CH;
    float v[6];
    float s = 0.f;
#pragma unroll
    for (int j = 0; j < 6; j++) { v[j] = xp[lane + 32 * j]; s += v[j]; }
#pragma unroll
    for (int o = 16; o > 0; o >>= 1) s += __shfl_xor_sync(0xffffffffu, s, o);
    float mean = s * (1.f / CH);
    float s2 = 0.f;
#pragma unroll
    for (int j = 0; j < 6; j++) { float d = v[j] - mean; s2 += d * d; }
#pragma unroll
    for (int o = 16; o > 0; o >>= 1) s2 += __shfl_xor_sync(0xffffffffu, s2, o);
    float rstd = rsqrtf(s2 * (1.f / CH) + 1e-5f);
    __half* op = out + (size_t)gwarp * CH;
#pragma unroll
    for (int j = 0; j < 6; j++) {
        int c = lane + 32 * j;
        op[c] = __float2half((v[j] - mean) * rstd * w[c] + bb[c]);
    }
}

// ---------------------------------------------------------------------------
// FP16 tensor-core GEMM via mma.sync.m16n8k16 + cp.async 4-stage pipeline.
// C[M,N] = A[M,K] @ W[N,K]^T, A/W fp16, accumulate fp32.
// CTA tile 128x96x32; 8 warps (4m x 2n), warp tile 32x48 (2x6 mma tiles).
// Smem row = 32 halves = 64B, stored at 80B stride (20 words): 20*r mod 32 is
// a permutation over 8 rows -> fragment LDS.32 fully bank-conflict-free.
// MODE 0: half  C = acc
// MODE 1: half  C = gelu(acc + bias)
// MODE 2: float C = resid_bchw + gamma[n]*(acc + bias)
// MODE 3: float C = resid_row  + gamma[n]*(acc + bias)  (in-place safe)
// MODE 4: float out_bchw = resid_row + gamma[n]*(acc + bias)
// ---------------------------------------------------------------------------
#define BM 128
#define BN 96
#define BK 32
#define STAGES 4
#define RSTRIDE 80                        // bytes per row in smem
#define A_ST_B (BM * RSTRIDE)             // 10240
#define B_ST_B (BN * RSTRIDE)             // 7680
#define ST_B   (A_ST_B + B_ST_B)          // 17920
#define GEMM_SMEM (STAGES * ST_B)         // 71680

__device__ __forceinline__ void cp16(uint32_t dst, const void* src) {
    asm volatile("cp.async.cg.shared.global [%0], [%1], 16;" :: "r"(dst), "l"(src) : "memory");
}

template<int MODE>
__global__ __launch_bounds__(256, 2)
void gemm_f16_kernel(const __half* __restrict__ A, const __half* __restrict__ W,
                     void* __restrict__ CoutV, int M, int N, int K,
                     const float* __restrict__ bias,
                     const float* __restrict__ gamma,
                     const float* __restrict__ resid) {
    extern __shared__ char sm[];
    const uint32_t smBase = smem_u32(sm);

    const int n0 = blockIdx.x * BN;
    const int m0 = blockIdx.y * BM;
    const int tid  = threadIdx.x;
    const int lane = tid & 31;
    const int wid  = tid >> 5;       // 0..7
    const int wm   = wid & 3;        // 0..3 -> 32 rows each
    const int wn   = wid >> 2;       // 0..1 -> 48 cols each

    float acc[2][6][4];
#pragma unroll
    for (int i = 0; i < 2; i++)
#pragma unroll
        for (int j = 0; j < 6; j++)
#pragma unroll
            for (int q = 0; q < 4; q++) acc[i][j][q] = 0.f;

    const int nK = K / BK;

    const int ldRow = tid >> 2;          // 0..63
    const int ldC   = tid & 3;           // 16B chunk (8 halves)

    auto load_stage = [&](int chunk, int st) {
        const int k0 = chunk * BK;
        const uint32_t aB = smBase + st * ST_B;
        const uint32_t bB = aB + A_ST_B;
#pragma unroll
        for (int it = 0; it < 2; it++) {
            int r = ldRow + it * 64;
            cp16(aB + r * RSTRIDE + (ldC << 4), A + (size_t)(m0 + r) * K + k0 + ldC * 8);
        }
        {
            int r = ldRow;
            cp16(bB + r * RSTRIDE + (ldC << 4), W + (size_t)(n0 + r) * K + k0 + ldC * 8);
        }
        if (tid < 128) {
            int r = 64 + ldRow;
            cp16(bB + r * RSTRIDE + (ldC << 4), W + (size_t)(n0 + r) * K + k0 + ldC * 8);
        }
        asm volatile("cp.async.commit_group;" ::: "memory");
    };

    load_stage(0, 0);
    load_stage(1, 1);
    load_stage(2, 2);

    const int fr  = lane >> 2;          // 0..7
    const uint32_t foff = (lane & 3) << 2;  // fq*4 bytes

    for (int kt = 0; kt < nK; kt++) {
        asm volatile("cp.async.wait_group %0;" :: "n"(STAGES - 2) : "memory");
        __syncthreads();

        if (kt + STAGES - 1 < nK) load_stage(kt + STAGES - 1, (kt + STAGES - 1) & (STAGES - 1));
        else asm volatile("cp.async.commit_group;" ::: "memory");

        const int st = kt & (STAGES - 1);
        const uint32_t aB = smBase + st * ST_B;
        const uint32_t bB = aB + A_ST_B;

#pragma unroll
        for (int g = 0; g < 2; g++) {       // two k16 halves of BK=32
            const uint32_t gk = g * 32;     // byte offset of k16 block in row
            uint32_t a[2][4];
#pragma unroll
            for (int i = 0; i < 2; i++) {
                int r0 = wm * 32 + i * 16 + fr;
                int r1 = r0 + 8;
                uint32_t p0 = aB + r0 * RSTRIDE + gk + foff;
                uint32_t p1 = aB + r1 * RSTRIDE + gk + foff;
                asm volatile("ld.shared.b32 %0, [%1];" : "=r"(a[i][0]) : "r"(p0));
                asm volatile("ld.shared.b32 %0, [%1];" : "=r"(a[i][1]) : "r"(p1));
                asm volatile("ld.shared.b32 %0, [%1];" : "=r"(a[i][2]) : "r"(p0 + 16));
                asm volatile("ld.shared.b32 %0, [%1];" : "=r"(a[i][3]) : "r"(p1 + 16));
            }
            uint32_t b[6][2];
#pragma unroll
            for (int j = 0; j < 6; j++) {
                int c = wn * 48 + j * 8 + fr;
                uint32_t p = bB + c * RSTRIDE + gk + foff;
                asm volatile("ld.shared.b32 %0, [%1];" : "=r"(b[j][0]) : "r"(p));
                asm volatile("ld.shared.b32 %0, [%1];" : "=r"(b[j][1]) : "r"(p + 16));
            }
#pragma unroll
            for (int i = 0; i < 2; i++)
#pragma unroll
                for (int j = 0; j < 6; j++) {
                    asm volatile(
                        "mma.sync.aligned.m16n8k16.row.col.f32.f16.f16.f32 "
                        "{%0,%1,%2,%3},{%4,%5,%6,%7},{%8,%9},{%0,%1,%2,%3};"
                        : "+f"(acc[i][j][0]), "+f"(acc[i][j][1]),
                          "+f"(acc[i][j][2]), "+f"(acc[i][j][3])
                        : "r"(a[i][0]), "r"(a[i][1]), "r"(a[i][2]), "r"(a[i][3]),
                          "r"(b[j][0]), "r"(b[j][1]));
                }
        }
        __syncthreads();
    }

    // ---- epilogue ----
    const int rq = lane >> 2;
    const int cq = (lane & 3) * 2;
    __half* Ch = (__half*)CoutV;
    float*  Cf = (float*)CoutV;
#pragma unroll
    for (int i = 0; i < 2; i++) {
#pragma unroll
        for (int j = 0; j < 6; j++) {
#pragma unroll
            for (int half_ = 0; half_ < 2; half_++) {
                int m = m0 + wm * 32 + i * 16 + rq + half_ * 8;
                int n = n0 + wn * 48 + j * 8 + cq;
                float v0 = acc[i][j][half_ * 2 + 0];
                float v1 = acc[i][j][half_ * 2 + 1];
                if (MODE == 0) {
                    *(__half2*)(Ch + (size_t)m * N + n) = __floats2half2_rn(v0, v1);
                } else if (MODE == 1) {
                    v0 += bias[n];     v1 += bias[n + 1];
                    v0 = 0.5f * v0 * (1.0f + erff(v0 * 0.70710678118654752f));
                    v1 = 0.5f * v1 * (1.0f + erff(v1 * 0.70710678118654752f));
                    *(__half2*)(Ch + (size_t)m * N + n) = __floats2half2_rn(v0, v1);
                } else if (MODE == 2) {
                    int bb_ = m >> 14, l = m & (HW - 1);
                    float r0 = resid[((size_t)(bb_ * CH + n)     << 14) + l];
                    float r1 = resid[((size_t)(bb_ * CH + n + 1) << 14) + l];
                    float2 o;
                    o.x = r0 + gamma[n]     * (v0 + bias[n]);
                    o.y = r1 + gamma[n + 1] * (v1 + bias[n + 1]);
                    *(float2*)(Cf + (size_t)m * N + n) = o;
                } else if (MODE == 3) {
                    float2 rr = *(const float2*)(resid + (size_t)m * N + n);
                    float2 o;
                    o.x = rr.x + gamma[n]     * (v0 + bias[n]);
                    o.y = rr.y + gamma[n + 1] * (v1 + bias[n + 1]);
                    *(float2*)(Cf + (size_t)m * N + n) = o;
                } else { // MODE 4
                    int bb_ = m >> 14, l = m & (HW - 1);
                    float r0 = resid[(size_t)m * N + n];
                    float r1 = resid[(size_t)m * N + n + 1];
                    Cf[((size_t)(bb_ * CH + n)     << 14) + l] = r0 + gamma[n]     * (v0 + bias[n]);
                    Cf[((size_t)(bb_ * CH + n + 1) << 14) + l] = r1 + gamma[n + 1] * (v1 + bias[n + 1]);
                }
            }
        }
    }
}

// ---------------------------------------------------------------------------
// Window attention (fp16 qkv in, fp16 att out; fp32 math inside)
// ---------------------------------------------------------------------------
__global__ __launch_bounds__(64)
void win_attn_kernel(const __half* __restrict__ qkv,
                     const float* __restrict__ table,
                     __half* __restrict__ out) {
    int h   = blockIdx.x & 7;
    int wid = blockIdx.x >> 3;
    int b   = wid >> 8;
    int rem = wid & 255;
    int wy  = rem >> 4, wx = rem & 15;

    int i  = threadIdx.x;
    int iy = i >> 3, ix = i & 7;
    int t  = (b << 14) + ((wy * 8 + iy) << 7) + wx * 8 + ix;

    __shared__ float ks[64][24];
    __shared__ float vs[64][24];
    __shared__ float bt[225];
    for (int p = i; p < 225; p += 64) bt[p] = table[p * NH + h];

    const __half* row = qkv + (size_t)t * (3 * CH) + h * HD;
    float q[24];
#pragma unroll
    for (int d = 0; d < HD; d++) {
        q[d]     = __half2float(row[d]);
        ks[i][d] = __half2float(row[CH + d]);
        vs[i][d] = __half2float(row[2 * CH + d]);
    }
    __syncthreads();

    const float scale = 0.20412414523193154f;
    float sc[64];
    float mx = -1e30f;
#pragma unroll 4
    for (int j = 0; j < 64; j++) {
        int jy = j >> 3, jx = j & 7;
        float dot = 0.f;
#pragma unroll
        for (int d = 0; d < HD; d++) dot += q[d] * ks[j][d];
        dot = dot * scale + bt[(iy - jy + 7) * 15 + (ix - jx + 7)];
        sc[j] = dot;
        mx = fmaxf(mx, dot);
    }
    float sum = 0.f;
#pragma unroll 4
    for (int j = 0; j < 64; j++) { sc[j] = __expf(sc[j] - mx); sum += sc[j]; }
    float inv = 1.f / sum;

    float accum[24];
#pragma unroll
    for (int d = 0; d < HD; d++) accum[d] = 0.f;
#pragma unroll 2
    for (int j = 0; j < 64; j++) {
        float p = sc[j];
#pragma unroll
        for (int d = 0; d < HD; d++) accum[d] += p * vs[j][d];
    }
    __half* op = out + (size_t)t * CH + h * HD;
#pragma unroll
    for (int d = 0; d < HD; d++) op[d] = __float2half(accum[d] * inv);
}

// ---------------------------------------------------------------------------
// Channel attention (fp16 qkv)
// ---------------------------------------------------------------------------
__global__ __launch_bounds__(576)
void ca_gram_kernel(const __half* __restrict__ qkv, float* __restrict__ gram) {
    int bh = blockIdx.x;
    int b = bh >> 3, h = bh & 7;
    int tid = threadIdx.x;
    int d = tid / 24, e = tid - d * 24;

    __shared__ float qs[64][24];
    __shared__ float ks[64][24];

    const int chunk = HW / 16;
    int l0 = blockIdx.y * chunk;
    float accum = 0.f;
    for (int tile = 0; tile < chunk; tile += 64) {
        for (int p = tid; p < 64 * 24; p += 576) {
            int tok = p / 24, dd = p - tok * 24;
            size_t base = (size_t)((b << 14) + l0 + tile + tok) * (3 * CH) + h * HD + dd;
            qs[tok][dd] = __half2float(qkv[base]);
            ks[tok][dd] = __half2float(qkv[base + CH]);
        }
        __syncthreads();
#pragma unroll 8
        for (int tok = 0; tok < 64; tok++) accum += qs[tok][d] * ks[tok][e];
        __syncthreads();
    }
    atomicAdd(&gram[bh * (HD * HD) + tid], accum);
}

__global__ void zero_gram_kernel(float* __restrict__ gram) {
    int i = blockIdx.x * blockDim.x + threadIdx.x;
    if (i < NH * BATCH * HD * HD) gram[i] = 0.f;
}

__global__ void ca_softmax_kernel(const float* __restrict__ gram, float* __restrict__ A) {
    int bh = blockIdx.x;
    int d = threadIdx.x;
    if (d >= HD) return;
    const float scale = 0.20412414523193154f;
    float r[24];
    float mx = -1e30f;
#pragma unroll
    for (int e = 0; e < HD; e++) {
        r[e] = gram[bh * (HD * HD) + d * HD + e] * scale;
        mx = fmaxf(mx, r[e]);
    }
    float sum = 0.f;
#pragma unroll
    for (int e = 0; e < HD; e++) { r[e] = __expf(r[e] - mx); sum += r[e]; }
    float inv = 1.f / sum;
#pragma unroll
    for (int e = 0; e < HD; e++) A[bh * (HD * HD) + d * HD + e] = r[e] * inv;
}

__global__ __launch_bounds__(256)
void ca_out_kernel(const __half* __restrict__ qkv, const float* __restrict__ A,
                   __half* __restrict__ out) {
    int b  = blockIdx.x;
    int l0 = blockIdx.y * 32;
    int tid = threadIdx.x;
    __shared__ float vs[32][192];
    for (int p = tid; p < 32 * 192; p += 256) {
        int tok = p / 192, c = p - tok * 192;
        vs[tok][c] = __half2float(qkv[(size_t)((b << 14) + l0 + tok) * (3 * CH) + 2 * CH + c]);
    }
    __syncthreads();
    int tok = tid >> 3;
    int h   = tid & 7;
    int t   = (b << 14) + l0 + tok;
    const float* Ah = A + (b * 8 + h) * (HD * HD);
    __half* op = out + (size_t)t * CH + h * HD;
#pragma unroll
    for (int d = 0; d < HD; d++) {
        float s = 0.f;
#pragma unroll
        for (int e = 0; e < HD; e++) s += Ah[d * HD + e] * vs[tok][h * HD + e];
        op[d] = __float2half(s);
    }
}

// ---------------------------------------------------------------------------
// Launch
// ---------------------------------------------------------------------------
extern "C" void kernel_launch(void* const* d_in, const int* in_sizes, int n_in,
                              void* d_out, int out_size) {
    const float* x          = (const float*)d_in[0];
    const float* sa_norm_w  = (const float*)d_in[1];
    const float* sa_norm_b  = (const float*)d_in[2];
    const float* sa_qkv_w   = (const float*)d_in[3];
    const float* sa_proj_w  = (const float*)d_in[4];
    const float* sa_proj_b  = (const float*)d_in[5];
    const float* sa_bias_t  = (const float*)d_in[6];
    const float* ca_norm_w  = (const float*)d_in[7];
    const float* ca_norm_b  = (const float*)d_in[8];
    const float* ca_qkv_w   = (const float*)d_in[9];
    const float* ca_proj_w  = (const float*)d_in[10];
    const float* ca_proj_b  = (const float*)d_in[11];
    const float* ffn_norm_w = (const float*)d_in[12];
    const float* ffn_norm_b = (const float*)d_in[13];
    const float* ffn_w1     = (const float*)d_in[14];
    const float* ffn_b1     = (const float*)d_in[15];
    const float* ffn_w2     = (const float*)d_in[16];
    const float* ffn_w2b    = (const float*)d_in[17];
    const float* gamma1     = (const float*)d_in[18];
    const float* gamma2     = (const float*)d_in[19];
    const float* gamma3     = (const float*)d_in[20];
    float* out = (float*)d_out;

    __half *xn, *qkv, *att, *h1, *wbuf;
    float *x1, *gram, *Amat;
    cudaGetSymbolAddress((void**)&xn,   g_xn);
    cudaGetSymbolAddress((void**)&qkv,  g_qkv);
    cudaGetSymbolAddress((void**)&att,  g_att);
    cudaGetSymbolAddress((void**)&h1,   g_h1);
    cudaGetSymbolAddress((void**)&x1,   g_x1);
    cudaGetSymbolAddress((void**)&gram, g_gram);
    cudaGetSymbolAddress((void**)&Amat, g_A);
    cudaGetSymbolAddress((void**)&wbuf, g_wbuf);

    const int smemB = GEMM_SMEM;  // 71680
    cudaFuncSetAttribute(gemm_f16_kernel<0>, cudaFuncAttributeMaxDynamicSharedMemorySize, smemB);
    cudaFuncSetAttribute(gemm_f16_kernel<1>, cudaFuncAttributeMaxDynamicSharedMemorySize, smemB);
    cudaFuncSetAttribute(gemm_f16_kernel<2>, cudaFuncAttributeMaxDynamicSharedMemorySize, smemB);
    cudaFuncSetAttribute(gemm_f16_kernel<3>, cudaFuncAttributeMaxDynamicSharedMemorySize, smemB);
    cudaFuncSetAttribute(gemm_f16_kernel<4>, cudaFuncAttributeMaxDynamicSharedMemorySize, smemB);

    // ---- weight conversions (fp32 -> fp16), cheap, every launch ----
    f2h_kernel<<<(3*CH*CH/4 + 255)/256, 256>>>(sa_qkv_w,  wbuf + W_SAQKV,  3*CH*CH/4);
    f2h_kernel<<<(CH*CH/4   + 255)/256, 256>>>(sa_proj_w, wbuf + W_SAPROJ, CH*CH/4);
    f2h_kernel<<<(3*CH*CH/4 + 255)/256, 256>>>(ca_qkv_w,  wbuf + W_CAQKV,  3*CH*CH/4);
    f2h_kernel<<<(CH*CH/4   + 255)/256, 256>>>(ca_proj_w, wbuf + W_CAPROJ, CH*CH/4);
    f2h_kernel<<<(FFN*CH/4  + 255)/256, 256>>>(ffn_w1,    wbuf + W_FFN1,   FFN*CH/4);
    f2h_kernel<<<(CH*FFN/4  + 255)/256, 256>>>(ffn_w2,    wbuf + W_FFN2,   CH*FFN/4);

    const int lnBlocks = TOK / 8;

    // ---- stage 1: window attention ----
    ln_bchw_kernel<<<lnBlocks, 256>>>(x, sa_norm_w, sa_norm_b, xn);
    gemm_f16_kernel<0><<<dim3(3 * CH / BN, TOK / BM), 256, smemB>>>(
        xn, wbuf + W_SAQKV, qkv, TOK, 3 * CH, CH, nullptr, nullptr, nullptr);
    win_attn_kernel<<<NWIN * NH, 64>>>(qkv, sa_bias_t, att);
    gemm_f16_kernel<2><<<dim3(CH / BN, TOK / BM), 256, smemB>>>(
        att, wbuf + W_SAPROJ, x1, TOK, CH, CH, sa_proj_b, gamma1, x);

    // ---- stage 2: channel attention ----
    ln_row_kernel<<<lnBlocks, 256>>>(x1, ca_norm_w, ca_norm_b, xn);
    gemm_f16_kernel<0><<<dim3(3 * CH / BN, TOK / BM), 256, smemB>>>(
        xn, wbuf + W_CAQKV, qkv, TOK, 3 * CH, CH, nullptr, nullptr, nullptr);
    zero_gram_kernel<<<(NH * BATCH * HD * HD + 255) / 256, 256>>>(gram);
    ca_gram_kernel<<<dim3(NH * BATCH, 16), 576>>>(qkv, gram);
    ca_softmax_kernel<<<NH * BATCH, 32>>>(gram, Amat);
    ca_out_kernel<<<dim3(BATCH, HW / 32), 256>>>(qkv, Amat, att);
    gemm_f16_kernel<3><<<dim3(CH / BN, TOK / BM), 256, smemB>>>(
        att, wbuf + W_CAPROJ, x1, TOK, CH, CH, ca_proj_b, gamma2, x1);

    // ---- stage 3: gated FFN ----
    ln_row_kernel<<<lnBlocks, 256>>>(x1, ffn_norm_w, ffn_norm_b, xn);
    gemm_f16_kernel<1><<<dim3(FFN / BN, TOK / BM), 256, smemB>>>(
        xn, wbuf + W_FFN1, h1, TOK, FFN, CH, ffn_b1, nullptr, nullptr);
    gemm_f16_kernel<4><<<dim3(CH / BN, TOK / BM), 256, smemB>>>(
        h1, wbuf + W_FFN2, out, TOK, CH, FFN, ffn_w2b, gamma3, x1);
}